// round 14
// baseline (speedup 1.0000x reference)
#include <cuda_runtime.h>
#include <cuda_bf16.h>
#include <math.h>
#include <stdint.h>

// Problem constants
#define BB 2
#define TT 1024
#define DD 2048
#define HH 16
#define DHD 128
#define RR (BB*TT)       // 2048
#define DHALF (DD/2)     // 1024
#define LCH 128
#define NC (TT/LCH)
#define BD (BB*DD)

#define KDIM 2048
#define NCHUNK (KDIM/32)                      // 64 chunks of 32 bf16 (64B rows)
#define STAGE_BYTES 32768                     // A hi/lo 8K+8K, B hi/lo 8K+8K
#define SMEM_GEMM (3*STAGE_BYTES + 1024)      // 3 stages ~97KB -> 2 CTAs/SM
#define SMEM_FLASH (65536 + 2*65536 + 1024)   // Q + 2 KV stages

// -------- fp32 scratch --------
__device__ float g_hdn[RR*DHALF];
__device__ float g_l2[RR*DD];
__device__ float g_fin[NC*BD];
__device__ float g_carry[NC*BD];

// -------- bf16 hi/lo scratch --------
__device__ __nv_bfloat16 g_xhi[RR*DD],  g_xlo[RR*DD];
__device__ __nv_bfloat16 g_qhi[RR*DD],  g_qlo[RR*DD];
__device__ __nv_bfloat16 g_fhi[RR*DD],  g_flo[RR*DD];
__device__ __nv_bfloat16 g_ahi[RR*DD],  g_alo[RR*DD];
__device__ __nv_bfloat16 g_khhi[RR*DD], g_khlo[RR*DD];   // [b,h,t,dh]
__device__ __nv_bfloat16 g_vhhi[RR*DD], g_vhlo[RR*DD];   // [b,h,t,dh]
__device__ __nv_bfloat16 g_wqhi[DD*DD], g_wqlo[DD*DD];
__device__ __nv_bfloat16 g_wkhi[DD*DD], g_wklo[DD*DD];
__device__ __nv_bfloat16 g_wvhi[DD*DD], g_wvlo[DD*DD];
__device__ __nv_bfloat16 g_wohi[DD*DD], g_wolo[DD*DD];
__device__ __nv_bfloat16 g_r1hi[DHALF*DD], g_r1lo[DHALF*DD];

// ================= PTX helpers =================
__device__ __forceinline__ uint32_t smem_u32(const void* p) {
    uint32_t a;
    asm("{ .reg .u64 t; cvta.to.shared.u64 t, %1; cvt.u32.u64 %0, t; }" : "=r"(a) : "l"(p));
    return a;
}
__device__ __forceinline__ void cpasync16(uint32_t s, const void* g) {
    asm volatile("cp.async.cg.shared.global [%0], [%1], 16;" :: "r"(s), "l"(g));
}
#define CP_COMMIT() asm volatile("cp.async.commit_group;" ::: "memory")
#define CP_WAIT(n)  asm volatile("cp.async.wait_group %0;" :: "n"(n) : "memory")

__device__ __forceinline__ void ldsm4(uint32_t* r, uint32_t addr) {
    asm volatile("ldmatrix.sync.aligned.m8n8.x4.shared.b16 {%0,%1,%2,%3}, [%4];"
        : "=r"(r[0]), "=r"(r[1]), "=r"(r[2]), "=r"(r[3]) : "r"(addr));
}
__device__ __forceinline__ void ldsm4t(uint32_t* r, uint32_t addr) {
    asm volatile("ldmatrix.sync.aligned.m8n8.x4.trans.shared.b16 {%0,%1,%2,%3}, [%4];"
        : "=r"(r[0]), "=r"(r[1]), "=r"(r[2]), "=r"(r[3]) : "r"(addr));
}
__device__ __forceinline__ void mma16816(float* c, const uint32_t* a, const uint32_t* b) {
    asm volatile(
        "mma.sync.aligned.m16n8k16.row.col.f32.bf16.bf16.f32 "
        "{%0,%1,%2,%3}, {%4,%5,%6,%7}, {%8,%9}, {%0,%1,%2,%3};"
        : "+f"(c[0]), "+f"(c[1]), "+f"(c[2]), "+f"(c[3])
        : "r"(a[0]), "r"(a[1]), "r"(a[2]), "r"(a[3]), "r"(b[0]), "r"(b[1]));
}
__device__ __forceinline__ void pack_hilo(float x, float y, uint32_t& hi, uint32_t& lo) {
    __nv_bfloat16 hx = __float2bfloat16(x), hy = __float2bfloat16(y);
    __nv_bfloat16 lx = __float2bfloat16(x - __bfloat162float(hx));
    __nv_bfloat16 ly = __float2bfloat16(y - __bfloat162float(hy));
    __nv_bfloat162 hp(hx, hy), lp(lx, ly);
    hi = *(uint32_t*)&hp; lo = *(uint32_t*)&lp;
}

// ================= fp32 -> bf16 hi/lo split (merged, 6 tensors) ============
struct CvtArgs {
    const float4* src[6];
    __nv_bfloat162* hi[6];
    __nv_bfloat162* lo[6];
    int n4[6];
};
__global__ void cvt_split_all(CvtArgs a) {
    int t = blockIdx.y;
    int i = blockIdx.x * blockDim.x + threadIdx.x;
    if (i >= a.n4[t]) return;
    float4 v = a.src[t][i];
    __nv_bfloat16 h0 = __float2bfloat16(v.x), h1 = __float2bfloat16(v.y);
    __nv_bfloat16 h2 = __float2bfloat16(v.z), h3 = __float2bfloat16(v.w);
    __nv_bfloat16 l0 = __float2bfloat16(v.x - __bfloat162float(h0));
    __nv_bfloat16 l1 = __float2bfloat16(v.y - __bfloat162float(h1));
    __nv_bfloat16 l2 = __float2bfloat16(v.z - __bfloat162float(h2));
    __nv_bfloat16 l3 = __float2bfloat16(v.w - __bfloat162float(h3));
    a.hi[t][2*i]   = __nv_bfloat162(h0, h1);
    a.hi[t][2*i+1] = __nv_bfloat162(h2, h3);
    a.lo[t][2*i]   = __nv_bfloat162(l0, l1);
    a.lo[t][2*i+1] = __nv_bfloat162(l2, l3);
}

// ================= HMMA GEMM: C = A * B^T (split bf16, fp32 acc) ===========
// 128x128 CTA tile, 128 threads (2x2 warps of 64x64), BK=32 (64B rows),
// 3-stage cp.async pipeline, ONE __syncthreads per chunk, 2 CTAs/SM.
// Grid for the big GEMMs = 256 CTAs <= 296 slots -> single wave.
// 64B-row swizzle: chunk j of row m at j ^ ((m>>1)&3).
// MODE 0: fp32 plain   MODE 1: bias+silu fp32
// MODE 4: bf16 hi/lo plain   MODE 5: fp32 scatter + bf16 hi/lo scatter [b,h,t,dh]
template<int MODE>
__global__ void __launch_bounds__(128, 2)
gemm_mma(const __nv_bfloat16* __restrict__ Ahi, const __nv_bfloat16* __restrict__ Alo,
         const __nv_bfloat16* __restrict__ Bhi, const __nv_bfloat16* __restrict__ Blo,
         float* __restrict__ C, __nv_bfloat16* __restrict__ Chi,
         __nv_bfloat16* __restrict__ Clo, int ldc, const float* __restrict__ bias) {
    extern __shared__ char dsm[];
    const int tid  = threadIdx.x;
    const int wid  = tid >> 5, lane = tid & 31;
    const int m0   = blockIdx.y * 128, n0 = blockIdx.x * 128;
    const int wm   = (wid & 1) * 64;
    const int wn   = (wid >> 1) * 64;
    uint32_t sb = (smem_u32(dsm) + 1023u) & ~1023u;

    const char* gA0 = (const char*)(Ahi + (size_t)m0 * KDIM);
    const char* gA1 = (const char*)(Alo + (size_t)m0 * KDIM);
    const char* gB0 = (const char*)(Bhi + (size_t)n0 * KDIM);
    const char* gB1 = (const char*)(Blo + (size_t)n0 * KDIM);

    // stage layout: Ahi@0(8K) Alo@8K Bhi@16K(8K) Blo@24K(8K); rows are 64B
    auto load_stage = [&](int s, int c) {
        uint32_t base = sb + (uint32_t)s * STAGE_BYTES;
        const int kb = c * 64;   // byte offset in K
        #pragma unroll
        for (int it = 0; it < 4; it++) {
            int idx = tid + it * 128;                  // 0..511 : rows 0..127, j 0..3
            int m = idx >> 2, j = idx & 3;
            uint32_t off = (uint32_t)m * 64u + (uint32_t)((j ^ ((m >> 1) & 3)) << 4);
            size_t go = (size_t)m * (KDIM * 2) + kb + j * 16;
            cpasync16(base + off,          gA0 + go);
            cpasync16(base + 8192u  + off, gA1 + go);
            cpasync16(base + 16384u + off, gB0 + go);
            cpasync16(base + 24576u + off, gB1 + go);
        }
        CP_COMMIT();
    };

    float acc[4][8][4];
    #pragma unroll
    for (int i = 0; i < 4; i++)
        #pragma unroll
        for (int j = 0; j < 8; j++)
            #pragma unroll
            for (int r = 0; r < 4; r++) acc[i][j][r] = 0.f;

    const int aRow0 = wm + ((lane >> 3) & 1) * 8 + (lane & 7);
    const int aKh   = (lane >> 4) & 1;
    const int bRow0 = wn + ((lane >> 4) & 1) * 8 + (lane & 7);
    const int bKh   = (lane >> 3) & 1;

    load_stage(0, 0);
    load_stage(1, 1);

    #pragma unroll 1
    for (int c = 0; c < NCHUNK; c++) {
        if (c == NCHUNK - 1) { CP_WAIT(0); } else { CP_WAIT(1); }
        __syncthreads();
        if (c + 2 < NCHUNK) {
            int s = c + 2; s -= (s / 3) * 3;   // (c+2) % 3
            load_stage(s, c + 2);
        }

        int cs = c - (c / 3) * 3;              // c % 3
        uint32_t base = sb + (uint32_t)cs * STAGE_BYTES;
        #pragma unroll
        for (int kk = 0; kk < 2; kk++) {
            uint32_t ah[4][4], al[4][4];
            #pragma unroll
            for (int mt = 0; mt < 4; mt++) {
                int row = aRow0 + mt * 16;
                int cc = (kk * 2 + aKh) ^ ((row >> 1) & 3);
                uint32_t off = (uint32_t)row * 64u + (uint32_t)cc * 16u;
                ldsm4(ah[mt], base + off);
                ldsm4(al[mt], base + 8192u + off);
            }
            #pragma unroll
            for (int g = 0; g < 4; g++) {
                uint32_t bh[4], bl[4];
                int row = bRow0 + g * 16;
                int cc = (kk * 2 + bKh) ^ ((row >> 1) & 3);
                uint32_t off = (uint32_t)row * 64u + (uint32_t)cc * 16u;
                ldsm4(bh, base + 16384u + off);
                ldsm4(bl, base + 24576u + off);
                #pragma unroll
                for (int i = 0; i < 4; i++)
                    #pragma unroll
                    for (int jj = 0; jj < 2; jj++) {
                        int j = g * 2 + jj;
                        mma16816(acc[i][j], ah[i], &bh[jj * 2]);
                        mma16816(acc[i][j], ah[i], &bl[jj * 2]);
                        mma16816(acc[i][j], al[i], &bh[jj * 2]);
                    }
            }
        }
    }

    // ---- vectorized epilogue ----
    #pragma unroll
    for (int i = 0; i < 4; i++) {
        #pragma unroll
        for (int j = 0; j < 8; j++) {
            #pragma unroll
            for (int rr = 0; rr < 2; rr++) {
                int row = m0 + wm + i * 16 + (lane >> 2) + rr * 8;
                int col = n0 + wn + j * 8 + (lane & 3) * 2;
                float v0 = acc[i][j][rr * 2 + 0];
                float v1 = acc[i][j][rr * 2 + 1];
                if (MODE == 0) {
                    *(float2*)(C + (size_t)row * ldc + col) = make_float2(v0, v1);
                } else if (MODE == 1) {
                    v0 += bias[col];     v1 += bias[col + 1];
                    v0 = v0 / (1.f + expf(-v0));
                    v1 = v1 / (1.f + expf(-v1));
                    *(float2*)(C + (size_t)row * ldc + col) = make_float2(v0, v1);
                } else if (MODE == 4) {
                    size_t idx = (size_t)row * ldc + col;
                    uint32_t hp, lp; pack_hilo(v0, v1, hp, lp);
                    *(uint32_t*)(Chi + idx) = hp;
                    *(uint32_t*)(Clo + idx) = lp;
                } else {  // MODE 5
                    int b = row >> 10, t = row & 1023;
                    int h = col >> 7,  jj = col & 127;
                    size_t idx = (((size_t)(b * HH + h)) * TT + t) * DHD + jj;
                    *(float2*)(C + idx) = make_float2(v0, v1);
                    uint32_t hp, lp; pack_hilo(v0, v1, hp, lp);
                    *(uint32_t*)(Chi + idx) = hp;
                    *(uint32_t*)(Clo + idx) = lp;
                }
            }
        }
    }
}

// ================= flash attention (fused S, softmax, PV) ==================
__global__ void __launch_bounds__(256, 1)
flash_attn(const __nv_bfloat16* __restrict__ khhi, const __nv_bfloat16* __restrict__ khlo,
           const __nv_bfloat16* __restrict__ vhhi, const __nv_bfloat16* __restrict__ vhlo) {
    extern __shared__ char dsm[];
    const int z  = blockIdx.x;
    const int qi = (int)gridDim.y - 1 - (int)blockIdx.y;
    const int b = z >> 4, h = z & 15;
    const int m0 = qi * 128;
    const int tid = threadIdx.x, wid = tid >> 5, lane = tid & 31;
    uint32_t sb = (smem_u32(dsm) + 1023u) & ~1023u;
    const uint32_t qs = sb;

    {
        const __nv_bfloat16* Qh = g_qhi + ((size_t)(b * TT) + m0) * DD + h * DHD;
        const __nv_bfloat16* Ql = g_qlo + ((size_t)(b * TT) + m0) * DD + h * DHD;
        #pragma unroll
        for (int it = 0; it < 8; it++) {
            int idx = tid + it * 256;
            int row = idx >> 4, u = idx & 15;
            uint32_t sa = qs + (uint32_t)row * 256u + (uint32_t)((u ^ (row & 7)) << 4);
            cpasync16(sa,           Qh + (size_t)row * DD + u * 8);
            cpasync16(sa + 32768u,  Ql + (size_t)row * DD + u * 8);
        }
    }
    const __nv_bfloat16* Kh = khhi + (size_t)z * TT * DHD;
    const __nv_bfloat16* Kl = khlo + (size_t)z * TT * DHD;
    const __nv_bfloat16* Vh = vhhi + (size_t)z * TT * DHD;
    const __nv_bfloat16* Vl = vhlo + (size_t)z * TT * DHD;

    auto load_kv = [&](int s, int ch) {
        uint32_t base = sb + 65536u + (uint32_t)s * 65536u;
        const __nv_bfloat16* srcs[4] = {
            Kh + (size_t)ch * 64 * DHD, Kl + (size_t)ch * 64 * DHD,
            Vh + (size_t)ch * 64 * DHD, Vl + (size_t)ch * 64 * DHD };
        #pragma unroll
        for (int tI = 0; tI < 4; tI++) {
            uint32_t tb = base + (uint32_t)tI * 16384u;
            const __nv_bfloat16* g = srcs[tI];
            #pragma unroll
            for (int it = 0; it < 4; it++) {
                int idx = tid + it * 256;
                int row = idx >> 4, u = idx & 15;
                cpasync16(tb + (uint32_t)row * 256u + (uint32_t)((u ^ (row & 7)) << 4),
                          g + (size_t)row * DHD + u * 8);
            }
        }
        CP_COMMIT();
    };

    const int nch = 2 * qi + 2;
    load_kv(0, 0);

    float m_[2] = {-1e30f, -1e30f}, l_[2] = {0.f, 0.f};
    float oacc[16][4];
    #pragma unroll
    for (int j = 0; j < 16; j++)
        #pragma unroll
        for (int r = 0; r < 4; r++) oacc[j][r] = 0.f;

    const int qrow_lo = wid * 16 + (lane >> 2);
    const float scale = 0.08838834764831845f;

    #pragma unroll 1
    for (int ch = 0; ch < nch; ch++) {
        if (ch + 1 < nch) {
            load_kv((ch + 1) & 1, ch + 1);
            CP_WAIT(1);
        } else {
            CP_WAIT(0);
        }
        __syncthreads();
        uint32_t kb = sb + 65536u + (uint32_t)(ch & 1) * 65536u;
        uint32_t vb = kb + 32768u;

        float sacc[8][4];
        #pragma unroll
        for (int j = 0; j < 8; j++)
            #pragma unroll
            for (int r = 0; r < 4; r++) sacc[j][r] = 0.f;

        #pragma unroll
        for (int kk = 0; kk < 8; kk++) {
            uint32_t ah[4], al[4];
            int arow = wid * 16 + ((lane >> 3) & 1) * 8 + (lane & 7);
            int au = (kk * 2 + ((lane >> 4) & 1)) ^ (arow & 7);
            uint32_t aoff = (uint32_t)arow * 256u + (uint32_t)au * 16u;
            ldsm4(ah, qs + aoff);
            ldsm4(al, qs + 32768u + aoff);
            #pragma unroll
            for (int g = 0; g < 4; g++) {
                uint32_t bh_[4], bl_[4];
                int brow = g * 16 + ((lane >> 4) & 1) * 8 + (lane & 7);
                int bu = (kk * 2 + ((lane >> 3) & 1)) ^ (brow & 7);
                uint32_t boff = (uint32_t)brow * 256u + (uint32_t)bu * 16u;
                ldsm4(bh_, kb + boff);
                ldsm4(bl_, kb + 16384u + boff);
                #pragma unroll
                for (int jj = 0; jj < 2; jj++) {
                    int j = g * 2 + jj;
                    mma16816(sacc[j], ah, &bh_[jj * 2]);
                    mma16816(sacc[j], ah, &bl_[jj * 2]);
                    mma16816(sacc[j], al, &bh_[jj * 2]);
                }
            }
        }

        const int kvbase = ch * 64;
        const bool maskp = (kvbase + 63 > m0);
        float mx[2] = {-1e30f, -1e30f};
        #pragma unroll
        for (int j = 0; j < 8; j++)
            #pragma unroll
            for (int r = 0; r < 4; r++) {
                float v = sacc[j][r] * scale;
                if (maskp) {
                    int col_g = kvbase + 8 * j + 2 * (lane & 3) + (r & 1);
                    int row_g = m0 + qrow_lo + (r >> 1) * 8;
                    if (col_g > row_g) v = -1e30f;
                }
                sacc[j][r] = v;
                mx[r >> 1] = fmaxf(mx[r >> 1], v);
            }
        #pragma unroll
        for (int rr = 0; rr < 2; rr++) {
            mx[rr] = fmaxf(mx[rr], __shfl_xor_sync(0xffffffffu, mx[rr], 1));
            mx[rr] = fmaxf(mx[rr], __shfl_xor_sync(0xffffffffu, mx[rr], 2));
        }
        float mn0 = fmaxf(m_[0], mx[0]), mn1 = fmaxf(m_[1], mx[1]);
        float al0 = __expf(m_[0] - mn0), al1 = __expf(m_[1] - mn1);
        float rs[2] = {0.f, 0.f};
        #pragma unroll
        for (int j = 0; j < 8; j++)
            #pragma unroll
            for (int r = 0; r < 4; r++) {
                float p = __expf(sacc[j][r] - ((r >> 1) ? mn1 : mn0));
                sacc[j][r] = p;
                rs[r >> 1] += p;
            }
        #pragma unroll
        for (int rr = 0; rr < 2; rr++) {
            rs[rr] += __shfl_xor_sync(0xffffffffu, rs[rr], 1);
            rs[rr] += __shfl_xor_sync(0xffffffffu, rs[rr], 2);
        }
        l_[0] = l_[0] * al0 + rs[0];
        l_[1] = l_[1] * al1 + rs[1];
        m_[0] = mn0; m_[1] = mn1;
        #pragma unroll
        for (int j = 0; j < 16; j++) {
            oacc[j][0] *= al0; oacc[j][1] *= al0;
            oacc[j][2] *= al1; oacc[j][3] *= al1;
        }

        #pragma unroll
        for (int kk = 0; kk < 4; kk++) {
            uint32_t aph[4], apl[4];
            pack_hilo(sacc[2*kk][0],   sacc[2*kk][1],   aph[0], apl[0]);
            pack_hilo(sacc[2*kk][2],   sacc[2*kk][3],   aph[1], apl[1]);
            pack_hilo(sacc[2*kk+1][0], sacc[2*kk+1][1], aph[2], apl[2]);
            pack_hilo(sacc[2*kk+1][2], sacc[2*kk+1][3], aph[3], apl[3]);
            int krow = kk * 16 + ((lane >> 3) & 1) * 8 + (lane & 7);
            #pragma unroll
            for (int ng = 0; ng < 8; ng++) {
                int nchk = ng * 2 + (lane >> 4);
                uint32_t addr = vb + (uint32_t)krow * 256u
                              + (uint32_t)((nchk ^ (krow & 7)) << 4);
                uint32_t bvh[4], bvl[4];
                ldsm4t(bvh, addr);
                ldsm4t(bvl, addr + 16384u);
                #pragma unroll
                for (int jj = 0; jj < 2; jj++) {
                    int j = ng * 2 + jj;
                    mma16816(oacc[j], aph, &bvh[jj * 2]);
                    mma16816(oacc[j], aph, &bvl[jj * 2]);
                    mma16816(oacc[j], apl, &bvh[jj * 2]);
                }
            }
        }
        __syncthreads();
    }

    float inv0 = 1.f / l_[0], inv1 = 1.f / l_[1];
    #pragma unroll
    for (int j = 0; j < 16; j++)
        #pragma unroll
        for (int rr = 0; rr < 2; rr++) {
            int t = m0 + qrow_lo + rr * 8;
            int col = 8 * j + 2 * (lane & 3);
            float inv = rr ? inv1 : inv0;
            float v0 = oacc[j][rr * 2 + 0] * inv;
            float v1 = oacc[j][rr * 2 + 1] * inv;
            size_t idx = ((size_t)(b * TT) + t) * DD + h * DHD + col;
            uint32_t hp, lp; pack_hilo(v0, v1, hp, lp);
            *(uint32_t*)(g_ahi + idx) = hp;
            *(uint32_t*)(g_alo + idx) = lp;
        }
}

// ================= EMA (chunked parallel scan) =================
__global__ void ema_pass1(const float* __restrict__ x) {
    int idx = blockIdx.x * blockDim.x + threadIdx.x;
    int d = idx % DD;
    int c = (idx / DD) % NC;
    int b = idx / (DD * NC);
    const float beta = 0.9f, om = 1.0f - 0.9f;
    size_t base = ((size_t)b * TT + (size_t)c * LCH) * DD + d;
    float s = 0.f;
    #pragma unroll 4
    for (int p = 0; p < LCH; p++) {
        s = beta * s + om * x[base + (size_t)p * DD];
        g_l2[base + (size_t)p * DD] = s;
    }
    g_fin[c * BD + b * DD + d] = s;
}
__global__ void ema_pass2() {
    int idx = blockIdx.x * blockDim.x + threadIdx.x;
    const float bl = __powf(0.9f, (float)LCH);
    float P = 0.f;
    g_carry[idx] = 0.f;
    for (int c = 1; c < NC; c++) {
        P = g_fin[(c - 1) * BD + idx] + bl * P;
        g_carry[c * BD + idx] = P;
    }
}

// ================= router + level fusion (emit bf16 hi/lo) =================
__global__ void router_fuse(const float* __restrict__ x,
                            const float* __restrict__ l3mem,
                            const float* __restrict__ rw2,
                            const float* __restrict__ rb2,
                            float* __restrict__ lam_out) {
    int r = blockIdx.x;
    int tid = threadIdx.x;
    int b = r / TT, t = r % TT;
    const float* hrow = g_hdn + (size_t)r * DHALF;

    float p0 = 0.f, p1 = 0.f, p2 = 0.f;
    for (int j = tid; j < DHALF; j += 256) {
        float h = hrow[j];
        p0 = fmaf(h, rw2[j], p0);
        p1 = fmaf(h, rw2[DHALF + j], p1);
        p2 = fmaf(h, rw2[2 * DHALF + j], p2);
    }
    #pragma unroll
    for (int o = 16; o; o >>= 1) {
        p0 += __shfl_xor_sync(0xffffffffu, p0, o);
        p1 += __shfl_xor_sync(0xffffffffu, p1, o);
        p2 += __shfl_xor_sync(0xffffffffu, p2, o);
    }
    __shared__ float red0[8], red1[8], red2[8];
    __shared__ float lam[3];
    int lane = tid & 31, w = tid >> 5;
    if (lane == 0) { red0[w] = p0; red1[w] = p1; red2[w] = p2; }
    __syncthreads();
    if (tid == 0) {
        float l0 = rb2[0], l1 = rb2[1], l2v = rb2[2];
        #pragma unroll
        for (int ww = 0; ww < 8; ww++) { l0 += red0[ww]; l1 += red1[ww]; l2v += red2[ww]; }
        float mx = fmaxf(l0, fmaxf(l1, l2v));
        float e0 = expf(l0 - mx), e1 = expf(l1 - mx), e2 = expf(l2v - mx);
        float inv = 1.f / (e0 + e1 + e2);
        lam[0] = e0 * inv; lam[1] = e1 * inv; lam[2] = e2 * inv;
        lam_out[r * 3 + 0] = lam[0];
        lam_out[r * 3 + 1] = lam[1];
        lam_out[r * 3 + 2] = lam[2];
    }
    __syncthreads();
    float la = lam[0], lb = lam[1], lcc = lam[2];

    int c = t / LCH, p = t % LCH;
    float pb = __powf(0.9f, (float)(p + 1));
    const float* carr = g_carry + c * BD + b * DD;
    size_t ro = (size_t)r * DD;
    for (int j = tid; j < DD; j += 256) {
        float l2v = g_l2[ro + j] + pb * carr[j];
        float v = la * x[ro + j] + lb * l2v + lcc * l3mem[b * DD + j];
        __nv_bfloat16 hv = __float2bfloat16(v);
        g_fhi[ro + j] = hv;
        g_flo[ro + j] = __float2bfloat16(v - __bfloat162float(hv));
    }
}

// ================= launch =================
extern "C" void kernel_launch(void* const* d_in, const int* in_sizes, int n_in,
                              void* d_out, int out_size) {
    (void)in_sizes; (void)n_in; (void)out_size;
    const float* x    = (const float*)d_in[0];
    const float* l3m  = (const float*)d_in[1];
    const float* wq   = (const float*)d_in[2];
    const float* wk   = (const float*)d_in[3];
    const float* wv   = (const float*)d_in[4];
    const float* wo   = (const float*)d_in[5];
    const float* rw1  = (const float*)d_in[6];
    const float* rb1  = (const float*)d_in[7];
    const float* rw2  = (const float*)d_in[8];
    const float* rb2  = (const float*)d_in[9];

    float* out     = (float*)d_out;
    float* kh_out  = out + (size_t)RR * DD;
    float* vh_out  = kh_out + (size_t)RR * DD;
    float* lam_out = vh_out + (size_t)RR * DD;

    float* hdn_;
    cudaGetSymbolAddress((void**)&hdn_, g_hdn);

    __nv_bfloat16 *xhi,*xlo,*qhi,*qlo,*fhi,*flo,*ahi,*alo,*khhi,*khlo,*vhhi,*vhlo;
    __nv_bfloat16 *wqh,*wql,*wkh,*wkl,*wvh,*wvl,*woh,*wol,*r1h,*r1l;
    cudaGetSymbolAddress((void**)&xhi, g_xhi);  cudaGetSymbolAddress((void**)&xlo, g_xlo);
    cudaGetSymbolAddress((void**)&qhi, g_qhi);  cudaGetSymbolAddress((void**)&qlo, g_qlo);
    cudaGetSymbolAddress((void**)&fhi, g_fhi);  cudaGetSymbolAddress((void**)&flo, g_flo);
    cudaGetSymbolAddress((void**)&ahi, g_ahi);  cudaGetSymbolAddress((void**)&alo, g_alo);
    cudaGetSymbolAddress((void**)&khhi, g_khhi); cudaGetSymbolAddress((void**)&khlo, g_khlo);
    cudaGetSymbolAddress((void**)&vhhi, g_vhhi); cudaGetSymbolAddress((void**)&vhlo, g_vhlo);
    cudaGetSymbolAddress((void**)&wqh, g_wqhi); cudaGetSymbolAddress((void**)&wql, g_wqlo);
    cudaGetSymbolAddress((void**)&wkh, g_wkhi); cudaGetSymbolAddress((void**)&wkl, g_wklo);
    cudaGetSymbolAddress((void**)&wvh, g_wvhi); cudaGetSymbolAddress((void**)&wvl, g_wvlo);
    cudaGetSymbolAddress((void**)&woh, g_wohi); cudaGetSymbolAddress((void**)&wol, g_wolo);
    cudaGetSymbolAddress((void**)&r1h, g_r1hi); cudaGetSymbolAddress((void**)&r1l, g_r1lo);

    cudaFuncSetAttribute(gemm_mma<0>, cudaFuncAttributeMaxDynamicSharedMemorySize, SMEM_GEMM);
    cudaFuncSetAttribute(gemm_mma<1>, cudaFuncAttributeMaxDynamicSharedMemorySize, SMEM_GEMM);
    cudaFuncSetAttribute(gemm_mma<4>, cudaFuncAttributeMaxDynamicSharedMemorySize, SMEM_GEMM);
    cudaFuncSetAttribute(gemm_mma<5>, cudaFuncAttributeMaxDynamicSharedMemorySize, SMEM_GEMM);
    cudaFuncSetAttribute(flash_attn,  cudaFuncAttributeMaxDynamicSharedMemorySize, SMEM_FLASH);

    const int NBIG = RR * DD / 4;
    const int NR1  = DHALF * DD / 4;

    // merged hi/lo splits of x + all weights
    CvtArgs ca;
    ca.src[0] = (const float4*)x;   ca.hi[0] = (__nv_bfloat162*)xhi; ca.lo[0] = (__nv_bfloat162*)xlo; ca.n4[0] = NBIG;
    ca.src[1] = (const float4*)wq;  ca.hi[1] = (__nv_bfloat162*)wqh; ca.lo[1] = (__nv_bfloat162*)wql; ca.n4[1] = NBIG;
    ca.src[2] = (const float4*)wk;  ca.hi[2] = (__nv_bfloat162*)wkh; ca.lo[2] = (__nv_bfloat162*)wkl; ca.n4[2] = NBIG;
    ca.src[3] = (const float4*)wv;  ca.hi[3] = (__nv_bfloat162*)wvh; ca.lo[3] = (__nv_bfloat162*)wvl; ca.n4[3] = NBIG;
    ca.src[4] = (const float4*)wo;  ca.hi[4] = (__nv_bfloat162*)woh; ca.lo[4] = (__nv_bfloat162*)wol; ca.n4[4] = NBIG;
    ca.src[5] = (const float4*)rw1; ca.hi[5] = (__nv_bfloat162*)r1h; ca.lo[5] = (__nv_bfloat162*)r1l; ca.n4[5] = NR1;
    cvt_split_all<<<dim3(NBIG/256, 6), 256>>>(ca);

    ema_pass1<<<BB * NC * DD / 256, 256>>>(x);
    ema_pass2<<<BD / 256, 256>>>();

    // q (bf16 hi/lo direct)
    gemm_mma<4><<<dim3(DD/128, RR/128), 128, SMEM_GEMM>>>(xhi, xlo, wqh, wql, nullptr, qhi, qlo, DD, nullptr);
    // hdn = silu(q @ rw1^T + rb1)
    gemm_mma<1><<<dim3(DHALF/128, RR/128), 128, SMEM_GEMM>>>(qhi, qlo, r1h, r1l, hdn_, nullptr, nullptr, DHALF, rb1);
    // router + fuse (emits fhi/flo)
    router_fuse<<<RR, 256>>>(x, l3m, rw2, rb2, lam_out);
    // K/V: fp32 head-layout outputs + bf16 hi/lo head layout
    gemm_mma<5><<<dim3(DD/128, RR/128), 128, SMEM_GEMM>>>(fhi, flo, wkh, wkl, kh_out, khhi, khlo, 0, nullptr);
    gemm_mma<5><<<dim3(DD/128, RR/128), 128, SMEM_GEMM>>>(fhi, flo, wvh, wvl, vh_out, vhhi, vhlo, 0, nullptr);
    // fused attention
    flash_attn<<<dim3(BB*HH, TT/128), 256, SMEM_FLASH>>>(khhi, khlo, vhhi, vhlo);
    // out = attno @ wo^T
    gemm_mma<0><<<dim3(DD/128, RR/128), 128, SMEM_GEMM>>>(ahi, alo, woh, wol, out, nullptr, nullptr, DD, nullptr);
}

// round 15
// speedup vs baseline: 1.1224x; 1.1224x over previous
#include <cuda_runtime.h>
#include <cuda_bf16.h>
#include <math.h>
#include <stdint.h>

// Problem constants
#define BB 2
#define TT 1024
#define DD 2048
#define HH 16
#define DHD 128
#define RR (BB*TT)       // 2048
#define DHALF (DD/2)     // 1024
#define LCH 128
#define NC (TT/LCH)
#define BD (BB*DD)

#define KDIM 2048
#define NCHUNK (KDIM/64)                      // 32 chunks of 64 bf16
#define STAGE_BYTES 49152                     // A hi/lo 8K+8K, B hi/lo 16K+16K
#define SMEM_GEMM (2*STAGE_BYTES + 1024)      // 97KB -> 2 CTAs/SM
#define SMEM_FLASH (65536 + 2*65536 + 1024)   // Q + 2 KV stages

// -------- fp32 scratch --------
__device__ float g_hdn[RR*DHALF];
__device__ float g_l2[RR*DD];
__device__ float g_fin[NC*BD];
__device__ float g_carry[NC*BD];

// -------- bf16 hi/lo scratch --------
__device__ __nv_bfloat16 g_xhi[RR*DD],  g_xlo[RR*DD];
__device__ __nv_bfloat16 g_qhi[RR*DD],  g_qlo[RR*DD];
__device__ __nv_bfloat16 g_fhi[RR*DD],  g_flo[RR*DD];
__device__ __nv_bfloat16 g_ahi[RR*DD],  g_alo[RR*DD];
__device__ __nv_bfloat16 g_khhi[RR*DD], g_khlo[RR*DD];   // [b,h,t,dh]
__device__ __nv_bfloat16 g_vhhi[RR*DD], g_vhlo[RR*DD];   // [b,h,t,dh]
__device__ __nv_bfloat16 g_wqhi[DD*DD], g_wqlo[DD*DD];
__device__ __nv_bfloat16 g_wkhi[DD*DD], g_wklo[DD*DD];
__device__ __nv_bfloat16 g_wvhi[DD*DD], g_wvlo[DD*DD];
__device__ __nv_bfloat16 g_wohi[DD*DD], g_wolo[DD*DD];
__device__ __nv_bfloat16 g_r1hi[DHALF*DD], g_r1lo[DHALF*DD];

// ================= PTX helpers =================
__device__ __forceinline__ uint32_t smem_u32(const void* p) {
    uint32_t a;
    asm("{ .reg .u64 t; cvta.to.shared.u64 t, %1; cvt.u32.u64 %0, t; }" : "=r"(a) : "l"(p));
    return a;
}
__device__ __forceinline__ void cpasync16(uint32_t s, const void* g) {
    asm volatile("cp.async.cg.shared.global [%0], [%1], 16;" :: "r"(s), "l"(g));
}
#define CP_COMMIT() asm volatile("cp.async.commit_group;" ::: "memory")
#define CP_WAIT(n)  asm volatile("cp.async.wait_group %0;" :: "n"(n) : "memory")

__device__ __forceinline__ void ldsm4(uint32_t* r, uint32_t addr) {
    asm volatile("ldmatrix.sync.aligned.m8n8.x4.shared.b16 {%0,%1,%2,%3}, [%4];"
        : "=r"(r[0]), "=r"(r[1]), "=r"(r[2]), "=r"(r[3]) : "r"(addr));
}
__device__ __forceinline__ void ldsm4t(uint32_t* r, uint32_t addr) {
    asm volatile("ldmatrix.sync.aligned.m8n8.x4.trans.shared.b16 {%0,%1,%2,%3}, [%4];"
        : "=r"(r[0]), "=r"(r[1]), "=r"(r[2]), "=r"(r[3]) : "r"(addr));
}
__device__ __forceinline__ void mma16816(float* c, const uint32_t* a, const uint32_t* b) {
    asm volatile(
        "mma.sync.aligned.m16n8k16.row.col.f32.bf16.bf16.f32 "
        "{%0,%1,%2,%3}, {%4,%5,%6,%7}, {%8,%9}, {%0,%1,%2,%3};"
        : "+f"(c[0]), "+f"(c[1]), "+f"(c[2]), "+f"(c[3])
        : "r"(a[0]), "r"(a[1]), "r"(a[2]), "r"(a[3]), "r"(b[0]), "r"(b[1]));
}
__device__ __forceinline__ void pack_hilo(float x, float y, uint32_t& hi, uint32_t& lo) {
    __nv_bfloat16 hx = __float2bfloat16(x), hy = __float2bfloat16(y);
    __nv_bfloat16 lx = __float2bfloat16(x - __bfloat162float(hx));
    __nv_bfloat16 ly = __float2bfloat16(y - __bfloat162float(hy));
    __nv_bfloat162 hp(hx, hy), lp(lx, ly);
    hi = *(uint32_t*)&hp; lo = *(uint32_t*)&lp;
}

// ================= fp32 -> bf16 hi/lo split (merged, 6 tensors) ============
struct CvtArgs {
    const float4* src[6];
    __nv_bfloat162* hi[6];
    __nv_bfloat162* lo[6];
    int n4[6];
};
__global__ void cvt_split_all(CvtArgs a) {
    int t = blockIdx.y;
    int i = blockIdx.x * blockDim.x + threadIdx.x;
    if (i >= a.n4[t]) return;
    float4 v = a.src[t][i];
    __nv_bfloat16 h0 = __float2bfloat16(v.x), h1 = __float2bfloat16(v.y);
    __nv_bfloat16 h2 = __float2bfloat16(v.z), h3 = __float2bfloat16(v.w);
    __nv_bfloat16 l0 = __float2bfloat16(v.x - __bfloat162float(h0));
    __nv_bfloat16 l1 = __float2bfloat16(v.y - __bfloat162float(h1));
    __nv_bfloat16 l2 = __float2bfloat16(v.z - __bfloat162float(h2));
    __nv_bfloat16 l3 = __float2bfloat16(v.w - __bfloat162float(h3));
    a.hi[t][2*i]   = __nv_bfloat162(h0, h1);
    a.hi[t][2*i+1] = __nv_bfloat162(h2, h3);
    a.lo[t][2*i]   = __nv_bfloat162(l0, l1);
    a.lo[t][2*i+1] = __nv_bfloat162(l2, l3);
}

// ================= shared GEMM core (R10 config) ===========================
// 64x128 CTA tile, 128 threads (2x2 warps of 32x64), BK=64, 2-stage pipeline.
struct GemmCore {
    uint32_t sb;
    int tid, wid, lane, wm, wn;
    int aRow0, aKh, bRow0, bKh;
    const char *gA0, *gA1, *gB0, *gB1;
    float acc[2][8][4];

    __device__ __forceinline__ void init(char* dsm, int m0, int n0,
        const __nv_bfloat16* Ahi, const __nv_bfloat16* Alo,
        const __nv_bfloat16* Bhi, const __nv_bfloat16* Blo) {
        tid = threadIdx.x; wid = tid >> 5; lane = tid & 31;
        wm = (wid & 1) * 32; wn = (wid >> 1) * 64;
        sb = (smem_u32(dsm) + 1023u) & ~1023u;
        gA0 = (const char*)(Ahi + (size_t)m0 * KDIM);
        gA1 = (const char*)(Alo + (size_t)m0 * KDIM);
        gB0 = (const char*)(Bhi + (size_t)n0 * KDIM);
        gB1 = (const char*)(Blo + (size_t)n0 * KDIM);
        #pragma unroll
        for (int i = 0; i < 2; i++)
            #pragma unroll
            for (int j = 0; j < 8; j++)
                #pragma unroll
                for (int r = 0; r < 4; r++) acc[i][j][r] = 0.f;
        aRow0 = wm + ((lane >> 3) & 1) * 8 + (lane & 7);
        aKh   = (lane >> 4) & 1;
        bRow0 = wn + ((lane >> 4) & 1) * 8 + (lane & 7);
        bKh   = (lane >> 3) & 1;
    }

    __device__ __forceinline__ void load_stage(int s, int k0) {
        uint32_t base = sb + (uint32_t)s * STAGE_BYTES;
        const int kb = k0 * 2;
        #pragma unroll
        for (int it = 0; it < 4; it++) {
            int idx = tid + it * 128;
            int m = idx >> 3, j = idx & 7;
            uint32_t off = (uint32_t)m * 128u + (uint32_t)((j ^ (m & 7)) << 4);
            size_t go = (size_t)m * (KDIM * 2) + kb + j * 16;
            cpasync16(base + off,         gA0 + go);
            cpasync16(base + 8192u + off, gA1 + go);
        }
        #pragma unroll
        for (int it = 0; it < 8; it++) {
            int idx = tid + it * 128;
            int m = idx >> 3, j = idx & 7;
            uint32_t off = (uint32_t)m * 128u + (uint32_t)((j ^ (m & 7)) << 4);
            size_t go = (size_t)m * (KDIM * 2) + kb + j * 16;
            cpasync16(base + 16384u + off, gB0 + go);
            cpasync16(base + 32768u + off, gB1 + go);
        }
        CP_COMMIT();
    }

    __device__ __forceinline__ void run() {
        load_stage(0, 0);
        load_stage(1, 64);
        #pragma unroll 1
        for (int c = 0; c < NCHUNK; c++) {
            if (c + 2 < NCHUNK) { CP_WAIT(1); } else { CP_WAIT(0); }
            __syncthreads();
            uint32_t base = sb + (uint32_t)(c & 1) * STAGE_BYTES;
            #pragma unroll
            for (int kk = 0; kk < 4; kk++) {
                uint32_t ah[2][4], al[2][4], bh[4][4], bl[4][4];
                #pragma unroll
                for (int mt = 0; mt < 2; mt++) {
                    int row = aRow0 + mt * 16;
                    int cc = (kk * 2 + aKh) ^ (row & 7);
                    uint32_t off = (uint32_t)row * 128u + (uint32_t)cc * 16u;
                    ldsm4(ah[mt], base + off);
                    ldsm4(al[mt], base + 8192u + off);
                }
                #pragma unroll
                for (int g = 0; g < 4; g++) {
                    int row = bRow0 + g * 16;
                    int cc = (kk * 2 + bKh) ^ (row & 7);
                    uint32_t off = (uint32_t)row * 128u + (uint32_t)cc * 16u;
                    ldsm4(bh[g], base + 16384u + off);
                    ldsm4(bl[g], base + 32768u + off);
                }
                #pragma unroll
                for (int i = 0; i < 2; i++)
                    #pragma unroll
                    for (int j = 0; j < 8; j++) {
                        const uint32_t* bph = &bh[j >> 1][(j & 1) * 2];
                        const uint32_t* bpl = &bl[j >> 1][(j & 1) * 2];
                        mma16816(acc[i][j], ah[i], bph);
                        mma16816(acc[i][j], ah[i], bpl);
                        mma16816(acc[i][j], al[i], bph);
                    }
            }
            __syncthreads();
            if (c + 2 < NCHUNK) load_stage(c & 1, (c + 2) * 64);
        }
    }
};

// ================= HMMA GEMM kernels =======================================
// MODE 0: fp32 plain   MODE 1: bias+silu fp32   MODE 4: bf16 hi/lo plain
template<int MODE>
__global__ void __launch_bounds__(128, 2)
gemm_mma(const __nv_bfloat16* __restrict__ Ahi, const __nv_bfloat16* __restrict__ Alo,
         const __nv_bfloat16* __restrict__ Bhi, const __nv_bfloat16* __restrict__ Blo,
         float* __restrict__ C, __nv_bfloat16* __restrict__ Chi,
         __nv_bfloat16* __restrict__ Clo, int ldc, const float* __restrict__ bias) {
    extern __shared__ char dsm[];
    const int m0 = blockIdx.y * 64, n0 = blockIdx.x * 128;
    GemmCore gc;
    gc.init(dsm, m0, n0, Ahi, Alo, Bhi, Blo);
    gc.run();

    #pragma unroll
    for (int i = 0; i < 2; i++) {
        #pragma unroll
        for (int j = 0; j < 8; j++) {
            #pragma unroll
            for (int rr = 0; rr < 2; rr++) {
                int row = m0 + gc.wm + i * 16 + (gc.lane >> 2) + rr * 8;
                int col = n0 + gc.wn + j * 8 + (gc.lane & 3) * 2;
                float v0 = gc.acc[i][j][rr * 2 + 0];
                float v1 = gc.acc[i][j][rr * 2 + 1];
                if (MODE == 0) {
                    *(float2*)(C + (size_t)row * ldc + col) = make_float2(v0, v1);
                } else if (MODE == 1) {
                    v0 += bias[col];     v1 += bias[col + 1];
                    v0 = v0 / (1.f + expf(-v0));
                    v1 = v1 / (1.f + expf(-v1));
                    *(float2*)(C + (size_t)row * ldc + col) = make_float2(v0, v1);
                } else {  // MODE 4
                    size_t idx = (size_t)row * ldc + col;
                    uint32_t hp, lp; pack_hilo(v0, v1, hp, lp);
                    *(uint32_t*)(Chi + idx) = hp;
                    *(uint32_t*)(Clo + idx) = lp;
                }
            }
        }
    }
}

// K and V projections merged into one launch: blockIdx.z selects the pair.
__global__ void __launch_bounds__(128, 2)
gemm_kv(const __nv_bfloat16* __restrict__ Ahi, const __nv_bfloat16* __restrict__ Alo,
        float* __restrict__ Ck, __nv_bfloat16* __restrict__ Ckhi, __nv_bfloat16* __restrict__ Cklo,
        float* __restrict__ Cv, __nv_bfloat16* __restrict__ Cvhi, __nv_bfloat16* __restrict__ Cvlo) {
    extern __shared__ char dsm[];
    const int m0 = blockIdx.y * 64, n0 = blockIdx.x * 128;
    const int zz = blockIdx.z;
    const __nv_bfloat16* Bhi = zz ? g_wvhi : g_wkhi;
    const __nv_bfloat16* Blo = zz ? g_wvlo : g_wklo;
    float* C            = zz ? Cv   : Ck;
    __nv_bfloat16* Chi  = zz ? Cvhi : Ckhi;
    __nv_bfloat16* Clo  = zz ? Cvlo : Cklo;

    GemmCore gc;
    gc.init(dsm, m0, n0, Ahi, Alo, Bhi, Blo);
    gc.run();

    #pragma unroll
    for (int i = 0; i < 2; i++) {
        #pragma unroll
        for (int j = 0; j < 8; j++) {
            #pragma unroll
            for (int rr = 0; rr < 2; rr++) {
                int row = m0 + gc.wm + i * 16 + (gc.lane >> 2) + rr * 8;
                int col = n0 + gc.wn + j * 8 + (gc.lane & 3) * 2;
                float v0 = gc.acc[i][j][rr * 2 + 0];
                float v1 = gc.acc[i][j][rr * 2 + 1];
                int b = row >> 10, t = row & 1023;
                int h = col >> 7,  jj = col & 127;
                size_t idx = (((size_t)(b * HH + h)) * TT + t) * DHD + jj;
                *(float2*)(C + idx) = make_float2(v0, v1);
                uint32_t hp, lp; pack_hilo(v0, v1, hp, lp);
                *(uint32_t*)(Chi + idx) = hp;
                *(uint32_t*)(Clo + idx) = lp;
            }
        }
    }
}

// ================= flash attention (fused S, softmax, PV) ==================
__global__ void __launch_bounds__(256, 1)
flash_attn(const __nv_bfloat16* __restrict__ khhi, const __nv_bfloat16* __restrict__ khlo,
           const __nv_bfloat16* __restrict__ vhhi, const __nv_bfloat16* __restrict__ vhlo) {
    extern __shared__ char dsm[];
    const int z  = blockIdx.x;
    const int qi = (int)gridDim.y - 1 - (int)blockIdx.y;
    const int b = z >> 4, h = z & 15;
    const int m0 = qi * 128;
    const int tid = threadIdx.x, wid = tid >> 5, lane = tid & 31;
    uint32_t sb = (smem_u32(dsm) + 1023u) & ~1023u;
    const uint32_t qs = sb;

    {
        const __nv_bfloat16* Qh = g_qhi + ((size_t)(b * TT) + m0) * DD + h * DHD;
        const __nv_bfloat16* Ql = g_qlo + ((size_t)(b * TT) + m0) * DD + h * DHD;
        #pragma unroll
        for (int it = 0; it < 8; it++) {
            int idx = tid + it * 256;
            int row = idx >> 4, u = idx & 15;
            uint32_t sa = qs + (uint32_t)row * 256u + (uint32_t)((u ^ (row & 7)) << 4);
            cpasync16(sa,           Qh + (size_t)row * DD + u * 8);
            cpasync16(sa + 32768u,  Ql + (size_t)row * DD + u * 8);
        }
    }
    const __nv_bfloat16* Kh = khhi + (size_t)z * TT * DHD;
    const __nv_bfloat16* Kl = khlo + (size_t)z * TT * DHD;
    const __nv_bfloat16* Vh = vhhi + (size_t)z * TT * DHD;
    const __nv_bfloat16* Vl = vhlo + (size_t)z * TT * DHD;

    auto load_kv = [&](int s, int ch) {
        uint32_t base = sb + 65536u + (uint32_t)s * 65536u;
        const __nv_bfloat16* srcs[4] = {
            Kh + (size_t)ch * 64 * DHD, Kl + (size_t)ch * 64 * DHD,
            Vh + (size_t)ch * 64 * DHD, Vl + (size_t)ch * 64 * DHD };
        #pragma unroll
        for (int tI = 0; tI < 4; tI++) {
            uint32_t tb = base + (uint32_t)tI * 16384u;
            const __nv_bfloat16* g = srcs[tI];
            #pragma unroll
            for (int it = 0; it < 4; it++) {
                int idx = tid + it * 256;
                int row = idx >> 4, u = idx & 15;
                cpasync16(tb + (uint32_t)row * 256u + (uint32_t)((u ^ (row & 7)) << 4),
                          g + (size_t)row * DHD + u * 8);
            }
        }
        CP_COMMIT();
    };

    const int nch = 2 * qi + 2;
    load_kv(0, 0);

    float m_[2] = {-1e30f, -1e30f}, l_[2] = {0.f, 0.f};
    float oacc[16][4];
    #pragma unroll
    for (int j = 0; j < 16; j++)
        #pragma unroll
        for (int r = 0; r < 4; r++) oacc[j][r] = 0.f;

    const int qrow_lo = wid * 16 + (lane >> 2);
    const float scale = 0.08838834764831845f;

    #pragma unroll 1
    for (int ch = 0; ch < nch; ch++) {
        if (ch + 1 < nch) {
            load_kv((ch + 1) & 1, ch + 1);
            CP_WAIT(1);
        } else {
            CP_WAIT(0);
        }
        __syncthreads();
        uint32_t kb = sb + 65536u + (uint32_t)(ch & 1) * 65536u;
        uint32_t vb = kb + 32768u;

        float sacc[8][4];
        #pragma unroll
        for (int j = 0; j < 8; j++)
            #pragma unroll
            for (int r = 0; r < 4; r++) sacc[j][r] = 0.f;

        #pragma unroll
        for (int kk = 0; kk < 8; kk++) {
            uint32_t ah[4], al[4];
            int arow = wid * 16 + ((lane >> 3) & 1) * 8 + (lane & 7);
            int au = (kk * 2 + ((lane >> 4) & 1)) ^ (arow & 7);
            uint32_t aoff = (uint32_t)arow * 256u + (uint32_t)au * 16u;
            ldsm4(ah, qs + aoff);
            ldsm4(al, qs + 32768u + aoff);
            #pragma unroll
            for (int g = 0; g < 4; g++) {
                uint32_t bh_[4], bl_[4];
                int brow = g * 16 + ((lane >> 4) & 1) * 8 + (lane & 7);
                int bu = (kk * 2 + ((lane >> 3) & 1)) ^ (brow & 7);
                uint32_t boff = (uint32_t)brow * 256u + (uint32_t)bu * 16u;
                ldsm4(bh_, kb + boff);
                ldsm4(bl_, kb + 16384u + boff);
                #pragma unroll
                for (int jj = 0; jj < 2; jj++) {
                    int j = g * 2 + jj;
                    mma16816(sacc[j], ah, &bh_[jj * 2]);
                    mma16816(sacc[j], ah, &bl_[jj * 2]);
                    mma16816(sacc[j], al, &bh_[jj * 2]);
                }
            }
        }

        const int kvbase = ch * 64;
        const bool maskp = (kvbase + 63 > m0);
        float mx[2] = {-1e30f, -1e30f};
        #pragma unroll
        for (int j = 0; j < 8; j++)
            #pragma unroll
            for (int r = 0; r < 4; r++) {
                float v = sacc[j][r] * scale;
                if (maskp) {
                    int col_g = kvbase + 8 * j + 2 * (lane & 3) + (r & 1);
                    int row_g = m0 + qrow_lo + (r >> 1) * 8;
                    if (col_g > row_g) v = -1e30f;
                }
                sacc[j][r] = v;
                mx[r >> 1] = fmaxf(mx[r >> 1], v);
            }
        #pragma unroll
        for (int rr = 0; rr < 2; rr++) {
            mx[rr] = fmaxf(mx[rr], __shfl_xor_sync(0xffffffffu, mx[rr], 1));
            mx[rr] = fmaxf(mx[rr], __shfl_xor_sync(0xffffffffu, mx[rr], 2));
        }
        float mn0 = fmaxf(m_[0], mx[0]), mn1 = fmaxf(m_[1], mx[1]);
        float al0 = __expf(m_[0] - mn0), al1 = __expf(m_[1] - mn1);
        float rs[2] = {0.f, 0.f};
        #pragma unroll
        for (int j = 0; j < 8; j++)
            #pragma unroll
            for (int r = 0; r < 4; r++) {
                float p = __expf(sacc[j][r] - ((r >> 1) ? mn1 : mn0));
                sacc[j][r] = p;
                rs[r >> 1] += p;
            }
        #pragma unroll
        for (int rr = 0; rr < 2; rr++) {
            rs[rr] += __shfl_xor_sync(0xffffffffu, rs[rr], 1);
            rs[rr] += __shfl_xor_sync(0xffffffffu, rs[rr], 2);
        }
        l_[0] = l_[0] * al0 + rs[0];
        l_[1] = l_[1] * al1 + rs[1];
        m_[0] = mn0; m_[1] = mn1;
        #pragma unroll
        for (int j = 0; j < 16; j++) {
            oacc[j][0] *= al0; oacc[j][1] *= al0;
            oacc[j][2] *= al1; oacc[j][3] *= al1;
        }

        #pragma unroll
        for (int kk = 0; kk < 4; kk++) {
            uint32_t aph[4], apl[4];
            pack_hilo(sacc[2*kk][0],   sacc[2*kk][1],   aph[0], apl[0]);
            pack_hilo(sacc[2*kk][2],   sacc[2*kk][3],   aph[1], apl[1]);
            pack_hilo(sacc[2*kk+1][0], sacc[2*kk+1][1], aph[2], apl[2]);
            pack_hilo(sacc[2*kk+1][2], sacc[2*kk+1][3], aph[3], apl[3]);
            int krow = kk * 16 + ((lane >> 3) & 1) * 8 + (lane & 7);
            #pragma unroll
            for (int ng = 0; ng < 8; ng++) {
                int nchk = ng * 2 + (lane >> 4);
                uint32_t addr = vb + (uint32_t)krow * 256u
                              + (uint32_t)((nchk ^ (krow & 7)) << 4);
                uint32_t bvh[4], bvl[4];
                ldsm4t(bvh, addr);
                ldsm4t(bvl, addr + 16384u);
                #pragma unroll
                for (int jj = 0; jj < 2; jj++) {
                    int j = ng * 2 + jj;
                    mma16816(oacc[j], aph, &bvh[jj * 2]);
                    mma16816(oacc[j], aph, &bvl[jj * 2]);
                    mma16816(oacc[j], apl, &bvh[jj * 2]);
                }
            }
        }
        __syncthreads();
    }

    float inv0 = 1.f / l_[0], inv1 = 1.f / l_[1];
    #pragma unroll
    for (int j = 0; j < 16; j++)
        #pragma unroll
        for (int rr = 0; rr < 2; rr++) {
            int t = m0 + qrow_lo + rr * 8;
            int col = 8 * j + 2 * (lane & 3);
            float inv = rr ? inv1 : inv0;
            float v0 = oacc[j][rr * 2 + 0] * inv;
            float v1 = oacc[j][rr * 2 + 1] * inv;
            size_t idx = ((size_t)(b * TT) + t) * DD + h * DHD + col;
            uint32_t hp, lp; pack_hilo(v0, v1, hp, lp);
            *(uint32_t*)(g_ahi + idx) = hp;
            *(uint32_t*)(g_alo + idx) = lp;
        }
}

// ================= EMA (chunked parallel scan) =================
__global__ void ema_pass1(const float* __restrict__ x) {
    int idx = blockIdx.x * blockDim.x + threadIdx.x;
    int d = idx % DD;
    int c = (idx / DD) % NC;
    int b = idx / (DD * NC);
    const float beta = 0.9f, om = 1.0f - 0.9f;
    size_t base = ((size_t)b * TT + (size_t)c * LCH) * DD + d;
    float s = 0.f;
    #pragma unroll 4
    for (int p = 0; p < LCH; p++) {
        s = beta * s + om * x[base + (size_t)p * DD];
        g_l2[base + (size_t)p * DD] = s;
    }
    g_fin[c * BD + b * DD + d] = s;
}
__global__ void ema_pass2() {
    int idx = blockIdx.x * blockDim.x + threadIdx.x;
    const float bl = __powf(0.9f, (float)LCH);
    float P = 0.f;
    g_carry[idx] = 0.f;
    for (int c = 1; c < NC; c++) {
        P = g_fin[(c - 1) * BD + idx] + bl * P;
        g_carry[c * BD + idx] = P;
    }
}

// ================= router + level fusion (emit bf16 hi/lo) =================
__global__ void router_fuse(const float* __restrict__ x,
                            const float* __restrict__ l3mem,
                            const float* __restrict__ rw2,
                            const float* __restrict__ rb2,
                            float* __restrict__ lam_out) {
    int r = blockIdx.x;
    int tid = threadIdx.x;
    int b = r / TT, t = r % TT;
    const float* hrow = g_hdn + (size_t)r * DHALF;

    float p0 = 0.f, p1 = 0.f, p2 = 0.f;
    for (int j = tid; j < DHALF; j += 256) {
        float h = hrow[j];
        p0 = fmaf(h, rw2[j], p0);
        p1 = fmaf(h, rw2[DHALF + j], p1);
        p2 = fmaf(h, rw2[2 * DHALF + j], p2);
    }
    #pragma unroll
    for (int o = 16; o; o >>= 1) {
        p0 += __shfl_xor_sync(0xffffffffu, p0, o);
        p1 += __shfl_xor_sync(0xffffffffu, p1, o);
        p2 += __shfl_xor_sync(0xffffffffu, p2, o);
    }
    __shared__ float red0[8], red1[8], red2[8];
    __shared__ float lam[3];
    int lane = tid & 31, w = tid >> 5;
    if (lane == 0) { red0[w] = p0; red1[w] = p1; red2[w] = p2; }
    __syncthreads();
    if (tid == 0) {
        float l0 = rb2[0], l1 = rb2[1], l2v = rb2[2];
        #pragma unroll
        for (int ww = 0; ww < 8; ww++) { l0 += red0[ww]; l1 += red1[ww]; l2v += red2[ww]; }
        float mx = fmaxf(l0, fmaxf(l1, l2v));
        float e0 = expf(l0 - mx), e1 = expf(l1 - mx), e2 = expf(l2v - mx);
        float inv = 1.f / (e0 + e1 + e2);
        lam[0] = e0 * inv; lam[1] = e1 * inv; lam[2] = e2 * inv;
        lam_out[r * 3 + 0] = lam[0];
        lam_out[r * 3 + 1] = lam[1];
        lam_out[r * 3 + 2] = lam[2];
    }
    __syncthreads();
    float la = lam[0], lb = lam[1], lcc = lam[2];

    int c = t / LCH, p = t % LCH;
    float pb = __powf(0.9f, (float)(p + 1));
    const float* carr = g_carry + c * BD + b * DD;
    size_t ro = (size_t)r * DD;
    for (int j = tid; j < DD; j += 256) {
        float l2v = g_l2[ro + j] + pb * carr[j];
        float v = la * x[ro + j] + lb * l2v + lcc * l3mem[b * DD + j];
        __nv_bfloat16 hv = __float2bfloat16(v);
        g_fhi[ro + j] = hv;
        g_flo[ro + j] = __float2bfloat16(v - __bfloat162float(hv));
    }
}

// ================= launch =================
extern "C" void kernel_launch(void* const* d_in, const int* in_sizes, int n_in,
                              void* d_out, int out_size) {
    (void)in_sizes; (void)n_in; (void)out_size;
    const float* x    = (const float*)d_in[0];
    const float* l3m  = (const float*)d_in[1];
    const float* wq   = (const float*)d_in[2];
    const float* wk   = (const float*)d_in[3];
    const float* wv   = (const float*)d_in[4];
    const float* wo   = (const float*)d_in[5];
    const float* rw1  = (const float*)d_in[6];
    const float* rb1  = (const float*)d_in[7];
    const float* rw2  = (const float*)d_in[8];
    const float* rb2  = (const float*)d_in[9];

    float* out     = (float*)d_out;
    float* kh_out  = out + (size_t)RR * DD;
    float* vh_out  = kh_out + (size_t)RR * DD;
    float* lam_out = vh_out + (size_t)RR * DD;

    float* hdn_;
    cudaGetSymbolAddress((void**)&hdn_, g_hdn);

    __nv_bfloat16 *xhi,*xlo,*qhi,*qlo,*fhi,*flo,*ahi,*alo,*khhi,*khlo,*vhhi,*vhlo;
    __nv_bfloat16 *wqh,*wql,*wkh,*wkl,*wvh,*wvl,*woh,*wol,*r1h,*r1l;
    cudaGetSymbolAddress((void**)&xhi, g_xhi);  cudaGetSymbolAddress((void**)&xlo, g_xlo);
    cudaGetSymbolAddress((void**)&qhi, g_qhi);  cudaGetSymbolAddress((void**)&qlo, g_qlo);
    cudaGetSymbolAddress((void**)&fhi, g_fhi);  cudaGetSymbolAddress((void**)&flo, g_flo);
    cudaGetSymbolAddress((void**)&ahi, g_ahi);  cudaGetSymbolAddress((void**)&alo, g_alo);
    cudaGetSymbolAddress((void**)&khhi, g_khhi); cudaGetSymbolAddress((void**)&khlo, g_khlo);
    cudaGetSymbolAddress((void**)&vhhi, g_vhhi); cudaGetSymbolAddress((void**)&vhlo, g_vhlo);
    cudaGetSymbolAddress((void**)&wqh, g_wqhi); cudaGetSymbolAddress((void**)&wql, g_wqlo);
    cudaGetSymbolAddress((void**)&wkh, g_wkhi); cudaGetSymbolAddress((void**)&wkl, g_wklo);
    cudaGetSymbolAddress((void**)&wvh, g_wvhi); cudaGetSymbolAddress((void**)&wvl, g_wvlo);
    cudaGetSymbolAddress((void**)&woh, g_wohi); cudaGetSymbolAddress((void**)&wol, g_wolo);
    cudaGetSymbolAddress((void**)&r1h, g_r1hi); cudaGetSymbolAddress((void**)&r1l, g_r1lo);

    cudaFuncSetAttribute(gemm_mma<0>, cudaFuncAttributeMaxDynamicSharedMemorySize, SMEM_GEMM);
    cudaFuncSetAttribute(gemm_mma<1>, cudaFuncAttributeMaxDynamicSharedMemorySize, SMEM_GEMM);
    cudaFuncSetAttribute(gemm_mma<4>, cudaFuncAttributeMaxDynamicSharedMemorySize, SMEM_GEMM);
    cudaFuncSetAttribute(gemm_kv,     cudaFuncAttributeMaxDynamicSharedMemorySize, SMEM_GEMM);
    cudaFuncSetAttribute(flash_attn,  cudaFuncAttributeMaxDynamicSharedMemorySize, SMEM_FLASH);

    const int NBIG = RR * DD / 4;
    const int NR1  = DHALF * DD / 4;

    // merged hi/lo splits of x + all weights
    CvtArgs ca;
    ca.src[0] = (const float4*)x;   ca.hi[0] = (__nv_bfloat162*)xhi; ca.lo[0] = (__nv_bfloat162*)xlo; ca.n4[0] = NBIG;
    ca.src[1] = (const float4*)wq;  ca.hi[1] = (__nv_bfloat162*)wqh; ca.lo[1] = (__nv_bfloat162*)wql; ca.n4[1] = NBIG;
    ca.src[2] = (const float4*)wk;  ca.hi[2] = (__nv_bfloat162*)wkh; ca.lo[2] = (__nv_bfloat162*)wkl; ca.n4[2] = NBIG;
    ca.src[3] = (const float4*)wv;  ca.hi[3] = (__nv_bfloat162*)wvh; ca.lo[3] = (__nv_bfloat162*)wvl; ca.n4[3] = NBIG;
    ca.src[4] = (const float4*)wo;  ca.hi[4] = (__nv_bfloat162*)woh; ca.lo[4] = (__nv_bfloat162*)wol; ca.n4[4] = NBIG;
    ca.src[5] = (const float4*)rw1; ca.hi[5] = (__nv_bfloat162*)r1h; ca.lo[5] = (__nv_bfloat162*)r1l; ca.n4[5] = NR1;
    cvt_split_all<<<dim3(NBIG/256, 6), 256>>>(ca);

    ema_pass1<<<BB * NC * DD / 256, 256>>>(x);
    ema_pass2<<<BD / 256, 256>>>();

    // q (bf16 hi/lo direct)
    gemm_mma<4><<<dim3(DD/128, RR/64), 128, SMEM_GEMM>>>(xhi, xlo, wqh, wql, nullptr, qhi, qlo, DD, nullptr);
    // hdn = silu(q @ rw1^T + rb1)
    gemm_mma<1><<<dim3(DHALF/128, RR/64), 128, SMEM_GEMM>>>(qhi, qlo, r1h, r1l, hdn_, nullptr, nullptr, DHALF, rb1);
    // router + fuse (emits fhi/flo)
    router_fuse<<<RR, 256>>>(x, l3m, rw2, rb2, lam_out);
    // K and V projections in ONE launch (z selects weight/output pair)
    gemm_kv<<<dim3(DD/128, RR/64, 2), 128, SMEM_GEMM>>>(fhi, flo,
        kh_out, khhi, khlo, vh_out, vhhi, vhlo);
    // fused attention
    flash_attn<<<dim3(BB*HH, TT/128), 256, SMEM_FLASH>>>(khhi, khlo, vhhi, vhlo);
    // out = attno @ wo^T
    gemm_mma<0><<<dim3(DD/128, RR/64), 128, SMEM_GEMM>>>(ahi, alo, woh, wol, out, nullptr, nullptr, DD, nullptr);
}

// round 16
// speedup vs baseline: 1.4966x; 1.3334x over previous
#include <cuda_runtime.h>
#include <cuda_bf16.h>
#include <cuda_fp16.h>
#include <math.h>
#include <stdint.h>

// Problem constants
#define BB 2
#define TT 1024
#define DD 2048
#define HH 16
#define DHD 128
#define RR (BB*TT)       // 2048
#define DHALF (DD/2)     // 1024
#define LCH 128
#define NC (TT/LCH)
#define BD (BB*DD)

#define KDIM 2048
#define NCHUNK (KDIM/64)                      // 32 chunks of 64 halves (128B rows)
#define STAGE_F16 32768                       // Ah 8K + Al 8K + Bh 16K
#define SMEM_GEMM (3*STAGE_F16 + 1024)        // 3 stages ~97KB -> 2 CTAs/SM
#define SMEM_FLASH (65536 + 2*65536 + 1024)   // Q + 2 KV stages

// -------- fp32 scratch --------
__device__ float g_hdn[RR*DHALF];
__device__ float g_l2[RR*DD];
__device__ float g_fin[NC*BD];
__device__ float g_carry[NC*BD];

// -------- fp16 scratch (2-product GEMM path) --------
__device__ __half g_x16h[RR*DD], g_x16l[RR*DD];
__device__ __half g_q16h[RR*DD], g_q16l[RR*DD];
__device__ __half g_f16h[RR*DD], g_f16l[RR*DD];
__device__ __half g_a16h[RR*DD], g_a16l[RR*DD];
__device__ __half g_wq16[DD*DD], g_wk16[DD*DD], g_wv16[DD*DD], g_wo16[DD*DD];
__device__ __half g_r116[DHALF*DD];

// -------- bf16 hi/lo scratch (flash attention path) --------
__device__ __nv_bfloat16 g_qhi[RR*DD],  g_qlo[RR*DD];
__device__ __nv_bfloat16 g_khhi[RR*DD], g_khlo[RR*DD];   // [b,h,t,dh]
__device__ __nv_bfloat16 g_vhhi[RR*DD], g_vhlo[RR*DD];   // [b,h,t,dh]

// ================= PTX helpers =================
__device__ __forceinline__ uint32_t smem_u32(const void* p) {
    uint32_t a;
    asm("{ .reg .u64 t; cvta.to.shared.u64 t, %1; cvt.u32.u64 %0, t; }" : "=r"(a) : "l"(p));
    return a;
}
__device__ __forceinline__ void cpasync16(uint32_t s, const void* g) {
    asm volatile("cp.async.cg.shared.global [%0], [%1], 16;" :: "r"(s), "l"(g));
}
#define CP_COMMIT() asm volatile("cp.async.commit_group;" ::: "memory")
#define CP_WAIT(n)  asm volatile("cp.async.wait_group %0;" :: "n"(n) : "memory")

__device__ __forceinline__ void ldsm4(uint32_t* r, uint32_t addr) {
    asm volatile("ldmatrix.sync.aligned.m8n8.x4.shared.b16 {%0,%1,%2,%3}, [%4];"
        : "=r"(r[0]), "=r"(r[1]), "=r"(r[2]), "=r"(r[3]) : "r"(addr));
}
__device__ __forceinline__ void ldsm4t(uint32_t* r, uint32_t addr) {
    asm volatile("ldmatrix.sync.aligned.m8n8.x4.trans.shared.b16 {%0,%1,%2,%3}, [%4];"
        : "=r"(r[0]), "=r"(r[1]), "=r"(r[2]), "=r"(r[3]) : "r"(addr));
}
__device__ __forceinline__ void mma16816(float* c, const uint32_t* a, const uint32_t* b) {
    asm volatile(
        "mma.sync.aligned.m16n8k16.row.col.f32.bf16.bf16.f32 "
        "{%0,%1,%2,%3}, {%4,%5,%6,%7}, {%8,%9}, {%0,%1,%2,%3};"
        : "+f"(c[0]), "+f"(c[1]), "+f"(c[2]), "+f"(c[3])
        : "r"(a[0]), "r"(a[1]), "r"(a[2]), "r"(a[3]), "r"(b[0]), "r"(b[1]));
}
__device__ __forceinline__ void mma16816h(float* c, const uint32_t* a, const uint32_t* b) {
    asm volatile(
        "mma.sync.aligned.m16n8k16.row.col.f32.f16.f16.f32 "
        "{%0,%1,%2,%3}, {%4,%5,%6,%7}, {%8,%9}, {%0,%1,%2,%3};"
        : "+f"(c[0]), "+f"(c[1]), "+f"(c[2]), "+f"(c[3])
        : "r"(a[0]), "r"(a[1]), "r"(a[2]), "r"(a[3]), "r"(b[0]), "r"(b[1]));
}
__device__ __forceinline__ void pack_hilo(float x, float y, uint32_t& hi, uint32_t& lo) {
    __nv_bfloat16 hx = __float2bfloat16(x), hy = __float2bfloat16(y);
    __nv_bfloat16 lx = __float2bfloat16(x - __bfloat162float(hx));
    __nv_bfloat16 ly = __float2bfloat16(y - __bfloat162float(hy));
    __nv_bfloat162 hp(hx, hy), lp(lx, ly);
    hi = *(uint32_t*)&hp; lo = *(uint32_t*)&lp;
}
__device__ __forceinline__ void pack_hilo_f16(float x, float y, uint32_t& hi, uint32_t& lo) {
    __half hx = __float2half_rn(x), hy = __float2half_rn(y);
    __half lx = __float2half_rn(x - __half2float(hx));
    __half ly = __float2half_rn(y - __half2float(hy));
    __half2 hp(hx, hy), lp(lx, ly);
    hi = *(uint32_t*)&hp; lo = *(uint32_t*)&lp;
}

// ============ conversion: x -> fp16 hi/lo split; weights -> fp16 hi only ===
struct CvtArgs {
    const float4* src[6];
    __half2* h[6];
    __half2* l[6];     // null for hi-only tensors
    int n4[6];
};
__global__ void cvt_all(CvtArgs a) {
    int t = blockIdx.y;
    int i = blockIdx.x * blockDim.x + threadIdx.x;
    if (i >= a.n4[t]) return;
    float4 v = a.src[t][i];
    __half h0 = __float2half_rn(v.x), h1 = __float2half_rn(v.y);
    __half h2 = __float2half_rn(v.z), h3 = __float2half_rn(v.w);
    a.h[t][2*i]   = __half2(h0, h1);
    a.h[t][2*i+1] = __half2(h2, h3);
    if (a.l[t]) {
        __half l0 = __float2half_rn(v.x - __half2float(h0));
        __half l1 = __float2half_rn(v.y - __half2float(h1));
        __half l2 = __float2half_rn(v.z - __half2float(h2));
        __half l3 = __float2half_rn(v.w - __half2float(h3));
        a.l[t][2*i]   = __half2(l0, l1);
        a.l[t][2*i+1] = __half2(l2, l3);
    }
}

// ================= fp16 2-product GEMM core =================================
// C = (Ah + Al) * Bh^T.  64x128 CTA tile, 128 threads (2x2 warps of 32x64),
// BK=64 halves (128B rows), 3-stage cp.async pipeline, ONE sync per chunk,
// 2 CTAs/SM.  Stage: Ah@0(8K) Al@8K Bh@16K(16K).
struct GemmF16 {
    uint32_t sb;
    int tid, wid, lane, wm, wn;
    int aRow0, aKh, bRow0, bKh;
    const char *gA0, *gA1, *gB0;
    float acc[2][8][4];

    __device__ __forceinline__ void init(char* dsm, int m0, int n0,
        const __half* Ah, const __half* Al, const __half* Bh) {
        tid = threadIdx.x; wid = tid >> 5; lane = tid & 31;
        wm = (wid & 1) * 32; wn = (wid >> 1) * 64;
        sb = (smem_u32(dsm) + 1023u) & ~1023u;
        gA0 = (const char*)(Ah + (size_t)m0 * KDIM);
        gA1 = (const char*)(Al + (size_t)m0 * KDIM);
        gB0 = (const char*)(Bh + (size_t)n0 * KDIM);
        #pragma unroll
        for (int i = 0; i < 2; i++)
            #pragma unroll
            for (int j = 0; j < 8; j++)
                #pragma unroll
                for (int r = 0; r < 4; r++) acc[i][j][r] = 0.f;
        aRow0 = wm + ((lane >> 3) & 1) * 8 + (lane & 7);
        aKh   = (lane >> 4) & 1;
        bRow0 = wn + ((lane >> 4) & 1) * 8 + (lane & 7);
        bKh   = (lane >> 3) & 1;
    }

    __device__ __forceinline__ void load_stage(int s, int c) {
        uint32_t base = sb + (uint32_t)s * STAGE_F16;
        const int kb = c * 128;   // byte offset in K (64 halves)
        #pragma unroll
        for (int it = 0; it < 4; it++) {
            int idx = tid + it * 128;                  // 0..511 : A rows 0..63
            int m = idx >> 3, j = idx & 7;
            uint32_t off = (uint32_t)m * 128u + (uint32_t)((j ^ (m & 7)) << 4);
            size_t go = (size_t)m * (KDIM * 2) + kb + j * 16;
            cpasync16(base + off,         gA0 + go);
            cpasync16(base + 8192u + off, gA1 + go);
        }
        #pragma unroll
        for (int it = 0; it < 8; it++) {
            int idx = tid + it * 128;                  // 0..1023 : B rows 0..127
            int m = idx >> 3, j = idx & 7;
            uint32_t off = (uint32_t)m * 128u + (uint32_t)((j ^ (m & 7)) << 4);
            size_t go = (size_t)m * (KDIM * 2) + kb + j * 16;
            cpasync16(base + 16384u + off, gB0 + go);
        }
        CP_COMMIT();
    }

    __device__ __forceinline__ void run() {
        load_stage(0, 0);
        load_stage(1, 1);
        #pragma unroll 1
        for (int c = 0; c < NCHUNK; c++) {
            if (c == NCHUNK - 1) { CP_WAIT(0); } else { CP_WAIT(1); }
            __syncthreads();
            if (c + 2 < NCHUNK) {
                int s = c + 2; s -= (s / 3) * 3;
                load_stage(s, c + 2);
            }
            int cs = c - (c / 3) * 3;
            uint32_t base = sb + (uint32_t)cs * STAGE_F16;
            #pragma unroll
            for (int kk = 0; kk < 4; kk++) {
                uint32_t ah[2][4], al[2][4];
                #pragma unroll
                for (int mt = 0; mt < 2; mt++) {
                    int row = aRow0 + mt * 16;
                    int cc = (kk * 2 + aKh) ^ (row & 7);
                    uint32_t off = (uint32_t)row * 128u + (uint32_t)cc * 16u;
                    ldsm4(ah[mt], base + off);
                    ldsm4(al[mt], base + 8192u + off);
                }
                #pragma unroll
                for (int g = 0; g < 4; g++) {
                    uint32_t bh[4];
                    int row = bRow0 + g * 16;
                    int cc = (kk * 2 + bKh) ^ (row & 7);
                    uint32_t off = (uint32_t)row * 128u + (uint32_t)cc * 16u;
                    ldsm4(bh, base + 16384u + off);
                    #pragma unroll
                    for (int i = 0; i < 2; i++)
                        #pragma unroll
                        for (int jj = 0; jj < 2; jj++) {
                            int j = g * 2 + jj;
                            mma16816h(acc[i][j], ah[i], &bh[jj * 2]);
                            mma16816h(acc[i][j], al[i], &bh[jj * 2]);
                        }
                }
            }
        }
    }
};

// ================= fp16 GEMM kernels =======================================
// MODE 0: fp32 plain (out)   MODE 1: bias+silu fp32 (hdn)
// MODE 2: Q — bf16 hi/lo (flash) + fp16 hi/lo (hdn input)
template<int MODE>
__global__ void __launch_bounds__(128, 2)
gemm_f16(const __half* __restrict__ Ah, const __half* __restrict__ Al,
         const __half* __restrict__ Bh,
         float* __restrict__ C, __nv_bfloat16* __restrict__ Chi,
         __nv_bfloat16* __restrict__ Clo, int ldc, const float* __restrict__ bias) {
    extern __shared__ char dsm[];
    const int m0 = blockIdx.y * 64, n0 = blockIdx.x * 128;
    GemmF16 gc;
    gc.init(dsm, m0, n0, Ah, Al, Bh);
    gc.run();

    #pragma unroll
    for (int i = 0; i < 2; i++) {
        #pragma unroll
        for (int j = 0; j < 8; j++) {
            #pragma unroll
            for (int rr = 0; rr < 2; rr++) {
                int row = m0 + gc.wm + i * 16 + (gc.lane >> 2) + rr * 8;
                int col = n0 + gc.wn + j * 8 + (gc.lane & 3) * 2;
                float v0 = gc.acc[i][j][rr * 2 + 0];
                float v1 = gc.acc[i][j][rr * 2 + 1];
                if (MODE == 0) {
                    *(float2*)(C + (size_t)row * ldc + col) = make_float2(v0, v1);
                } else if (MODE == 1) {
                    v0 += bias[col];     v1 += bias[col + 1];
                    v0 = v0 / (1.f + expf(-v0));
                    v1 = v1 / (1.f + expf(-v1));
                    *(float2*)(C + (size_t)row * ldc + col) = make_float2(v0, v1);
                } else {  // MODE 2 (Q)
                    size_t idx = (size_t)row * ldc + col;
                    uint32_t hp, lp; pack_hilo(v0, v1, hp, lp);
                    *(uint32_t*)(Chi + idx) = hp;
                    *(uint32_t*)(Clo + idx) = lp;
                    uint32_t h16, l16; pack_hilo_f16(v0, v1, h16, l16);
                    *(uint32_t*)(g_q16h + idx) = h16;
                    *(uint32_t*)(g_q16l + idx) = l16;
                }
            }
        }
    }
}

// K and V projections merged into one launch (z selects pair), fp16 2-product.
__global__ void __launch_bounds__(128, 2)
gemm_kv_f16(const __half* __restrict__ Ah, const __half* __restrict__ Al,
            float* __restrict__ Ck, __nv_bfloat16* __restrict__ Ckhi, __nv_bfloat16* __restrict__ Cklo,
            float* __restrict__ Cv, __nv_bfloat16* __restrict__ Cvhi, __nv_bfloat16* __restrict__ Cvlo) {
    extern __shared__ char dsm[];
    const int m0 = blockIdx.y * 64, n0 = blockIdx.x * 128;
    const int zz = blockIdx.z;
    const __half* Bh = zz ? g_wv16 : g_wk16;
    float* C            = zz ? Cv   : Ck;
    __nv_bfloat16* Chi  = zz ? Cvhi : Ckhi;
    __nv_bfloat16* Clo  = zz ? Cvlo : Cklo;

    GemmF16 gc;
    gc.init(dsm, m0, n0, Ah, Al, Bh);
    gc.run();

    #pragma unroll
    for (int i = 0; i < 2; i++) {
        #pragma unroll
        for (int j = 0; j < 8; j++) {
            #pragma unroll
            for (int rr = 0; rr < 2; rr++) {
                int row = m0 + gc.wm + i * 16 + (gc.lane >> 2) + rr * 8;
                int col = n0 + gc.wn + j * 8 + (gc.lane & 3) * 2;
                float v0 = gc.acc[i][j][rr * 2 + 0];
                float v1 = gc.acc[i][j][rr * 2 + 1];
                int b = row >> 10, t = row & 1023;
                int h = col >> 7,  jj = col & 127;
                size_t idx = (((size_t)(b * HH + h)) * TT + t) * DHD + jj;
                *(float2*)(C + idx) = make_float2(v0, v1);
                uint32_t hp, lp; pack_hilo(v0, v1, hp, lp);
                *(uint32_t*)(Chi + idx) = hp;
                *(uint32_t*)(Clo + idx) = lp;
            }
        }
    }
}

// ================= flash attention (fused S, softmax, PV; bf16 3-product) ==
__global__ void __launch_bounds__(256, 1)
flash_attn(const __nv_bfloat16* __restrict__ khhi, const __nv_bfloat16* __restrict__ khlo,
           const __nv_bfloat16* __restrict__ vhhi, const __nv_bfloat16* __restrict__ vhlo) {
    extern __shared__ char dsm[];
    const int z  = blockIdx.x;
    const int qi = (int)gridDim.y - 1 - (int)blockIdx.y;
    const int b = z >> 4, h = z & 15;
    const int m0 = qi * 128;
    const int tid = threadIdx.x, wid = tid >> 5, lane = tid & 31;
    uint32_t sb = (smem_u32(dsm) + 1023u) & ~1023u;
    const uint32_t qs = sb;

    {
        const __nv_bfloat16* Qh = g_qhi + ((size_t)(b * TT) + m0) * DD + h * DHD;
        const __nv_bfloat16* Ql = g_qlo + ((size_t)(b * TT) + m0) * DD + h * DHD;
        #pragma unroll
        for (int it = 0; it < 8; it++) {
            int idx = tid + it * 256;
            int row = idx >> 4, u = idx & 15;
            uint32_t sa = qs + (uint32_t)row * 256u + (uint32_t)((u ^ (row & 7)) << 4);
            cpasync16(sa,           Qh + (size_t)row * DD + u * 8);
            cpasync16(sa + 32768u,  Ql + (size_t)row * DD + u * 8);
        }
    }
    const __nv_bfloat16* Kh = khhi + (size_t)z * TT * DHD;
    const __nv_bfloat16* Kl = khlo + (size_t)z * TT * DHD;
    const __nv_bfloat16* Vh = vhhi + (size_t)z * TT * DHD;
    const __nv_bfloat16* Vl = vhlo + (size_t)z * TT * DHD;

    auto load_kv = [&](int s, int ch) {
        uint32_t base = sb + 65536u + (uint32_t)s * 65536u;
        const __nv_bfloat16* srcs[4] = {
            Kh + (size_t)ch * 64 * DHD, Kl + (size_t)ch * 64 * DHD,
            Vh + (size_t)ch * 64 * DHD, Vl + (size_t)ch * 64 * DHD };
        #pragma unroll
        for (int tI = 0; tI < 4; tI++) {
            uint32_t tb = base + (uint32_t)tI * 16384u;
            const __nv_bfloat16* g = srcs[tI];
            #pragma unroll
            for (int it = 0; it < 4; it++) {
                int idx = tid + it * 256;
                int row = idx >> 4, u = idx & 15;
                cpasync16(tb + (uint32_t)row * 256u + (uint32_t)((u ^ (row & 7)) << 4),
                          g + (size_t)row * DHD + u * 8);
            }
        }
        CP_COMMIT();
    };

    const int nch = 2 * qi + 2;
    load_kv(0, 0);

    float m_[2] = {-1e30f, -1e30f}, l_[2] = {0.f, 0.f};
    float oacc[16][4];
    #pragma unroll
    for (int j = 0; j < 16; j++)
        #pragma unroll
        for (int r = 0; r < 4; r++) oacc[j][r] = 0.f;

    const int qrow_lo = wid * 16 + (lane >> 2);
    const float scale = 0.08838834764831845f;

    #pragma unroll 1
    for (int ch = 0; ch < nch; ch++) {
        if (ch + 1 < nch) {
            load_kv((ch + 1) & 1, ch + 1);
            CP_WAIT(1);
        } else {
            CP_WAIT(0);
        }
        __syncthreads();
        uint32_t kb = sb + 65536u + (uint32_t)(ch & 1) * 65536u;
        uint32_t vb = kb + 32768u;

        float sacc[8][4];
        #pragma unroll
        for (int j = 0; j < 8; j++)
            #pragma unroll
            for (int r = 0; r < 4; r++) sacc[j][r] = 0.f;

        #pragma unroll
        for (int kk = 0; kk < 8; kk++) {
            uint32_t ah[4], al[4];
            int arow = wid * 16 + ((lane >> 3) & 1) * 8 + (lane & 7);
            int au = (kk * 2 + ((lane >> 4) & 1)) ^ (arow & 7);
            uint32_t aoff = (uint32_t)arow * 256u + (uint32_t)au * 16u;
            ldsm4(ah, qs + aoff);
            ldsm4(al, qs + 32768u + aoff);
            #pragma unroll
            for (int g = 0; g < 4; g++) {
                uint32_t bh_[4], bl_[4];
                int brow = g * 16 + ((lane >> 4) & 1) * 8 + (lane & 7);
                int bu = (kk * 2 + ((lane >> 3) & 1)) ^ (brow & 7);
                uint32_t boff = (uint32_t)brow * 256u + (uint32_t)bu * 16u;
                ldsm4(bh_, kb + boff);
                ldsm4(bl_, kb + 16384u + boff);
                #pragma unroll
                for (int jj = 0; jj < 2; jj++) {
                    int j = g * 2 + jj;
                    mma16816(sacc[j], ah, &bh_[jj * 2]);
                    mma16816(sacc[j], ah, &bl_[jj * 2]);
                    mma16816(sacc[j], al, &bh_[jj * 2]);
                }
            }
        }

        const int kvbase = ch * 64;
        const bool maskp = (kvbase + 63 > m0);
        float mx[2] = {-1e30f, -1e30f};
        #pragma unroll
        for (int j = 0; j < 8; j++)
            #pragma unroll
            for (int r = 0; r < 4; r++) {
                float v = sacc[j][r] * scale;
                if (maskp) {
                    int col_g = kvbase + 8 * j + 2 * (lane & 3) + (r & 1);
                    int row_g = m0 + qrow_lo + (r >> 1) * 8;
                    if (col_g > row_g) v = -1e30f;
                }
                sacc[j][r] = v;
                mx[r >> 1] = fmaxf(mx[r >> 1], v);
            }
        #pragma unroll
        for (int rr = 0; rr < 2; rr++) {
            mx[rr] = fmaxf(mx[rr], __shfl_xor_sync(0xffffffffu, mx[rr], 1));
            mx[rr] = fmaxf(mx[rr], __shfl_xor_sync(0xffffffffu, mx[rr], 2));
        }
        float mn0 = fmaxf(m_[0], mx[0]), mn1 = fmaxf(m_[1], mx[1]);
        float al0 = __expf(m_[0] - mn0), al1 = __expf(m_[1] - mn1);
        float rs[2] = {0.f, 0.f};
        #pragma unroll
        for (int j = 0; j < 8; j++)
            #pragma unroll
            for (int r = 0; r < 4; r++) {
                float p = __expf(sacc[j][r] - ((r >> 1) ? mn1 : mn0));
                sacc[j][r] = p;
                rs[r >> 1] += p;
            }
        #pragma unroll
        for (int rr = 0; rr < 2; rr++) {
            rs[rr] += __shfl_xor_sync(0xffffffffu, rs[rr], 1);
            rs[rr] += __shfl_xor_sync(0xffffffffu, rs[rr], 2);
        }
        l_[0] = l_[0] * al0 + rs[0];
        l_[1] = l_[1] * al1 + rs[1];
        m_[0] = mn0; m_[1] = mn1;
        #pragma unroll
        for (int j = 0; j < 16; j++) {
            oacc[j][0] *= al0; oacc[j][1] *= al0;
            oacc[j][2] *= al1; oacc[j][3] *= al1;
        }

        #pragma unroll
        for (int kk = 0; kk < 4; kk++) {
            uint32_t aph[4], apl[4];
            pack_hilo(sacc[2*kk][0],   sacc[2*kk][1],   aph[0], apl[0]);
            pack_hilo(sacc[2*kk][2],   sacc[2*kk][3],   aph[1], apl[1]);
            pack_hilo(sacc[2*kk+1][0], sacc[2*kk+1][1], aph[2], apl[2]);
            pack_hilo(sacc[2*kk+1][2], sacc[2*kk+1][3], aph[3], apl[3]);
            int krow = kk * 16 + ((lane >> 3) & 1) * 8 + (lane & 7);
            #pragma unroll
            for (int ng = 0; ng < 8; ng++) {
                int nchk = ng * 2 + (lane >> 4);
                uint32_t addr = vb + (uint32_t)krow * 256u
                              + (uint32_t)((nchk ^ (krow & 7)) << 4);
                uint32_t bvh[4], bvl[4];
                ldsm4t(bvh, addr);
                ldsm4t(bvl, addr + 16384u);
                #pragma unroll
                for (int jj = 0; jj < 2; jj++) {
                    int j = ng * 2 + jj;
                    mma16816(oacc[j], aph, &bvh[jj * 2]);
                    mma16816(oacc[j], aph, &bvl[jj * 2]);
                    mma16816(oacc[j], apl, &bvh[jj * 2]);
                }
            }
        }
        __syncthreads();
    }

    // epilogue: attno as fp16 hi/lo for the out-projection
    float inv0 = 1.f / l_[0], inv1 = 1.f / l_[1];
    #pragma unroll
    for (int j = 0; j < 16; j++)
        #pragma unroll
        for (int rr = 0; rr < 2; rr++) {
            int t = m0 + qrow_lo + rr * 8;
            int col = 8 * j + 2 * (lane & 3);
            float inv = rr ? inv1 : inv0;
            float v0 = oacc[j][rr * 2 + 0] * inv;
            float v1 = oacc[j][rr * 2 + 1] * inv;
            size_t idx = ((size_t)(b * TT) + t) * DD + h * DHD + col;
            uint32_t hp, lp; pack_hilo_f16(v0, v1, hp, lp);
            *(uint32_t*)(g_a16h + idx) = hp;
            *(uint32_t*)(g_a16l + idx) = lp;
        }
}

// ================= EMA (chunked parallel scan) =================
__global__ void ema_pass1(const float* __restrict__ x) {
    int idx = blockIdx.x * blockDim.x + threadIdx.x;
    int d = idx % DD;
    int c = (idx / DD) % NC;
    int b = idx / (DD * NC);
    const float beta = 0.9f, om = 1.0f - 0.9f;
    size_t base = ((size_t)b * TT + (size_t)c * LCH) * DD + d;
    float s = 0.f;
    #pragma unroll 4
    for (int p = 0; p < LCH; p++) {
        s = beta * s + om * x[base + (size_t)p * DD];
        g_l2[base + (size_t)p * DD] = s;
    }
    g_fin[c * BD + b * DD + d] = s;
}
__global__ void ema_pass2() {
    int idx = blockIdx.x * blockDim.x + threadIdx.x;
    const float bl = __powf(0.9f, (float)LCH);
    float P = 0.f;
    g_carry[idx] = 0.f;
    for (int c = 1; c < NC; c++) {
        P = g_fin[(c - 1) * BD + idx] + bl * P;
        g_carry[c * BD + idx] = P;
    }
}

// ================= router + level fusion (emit fp16 hi/lo) =================
__global__ void router_fuse(const float* __restrict__ x,
                            const float* __restrict__ l3mem,
                            const float* __restrict__ rw2,
                            const float* __restrict__ rb2,
                            float* __restrict__ lam_out) {
    int r = blockIdx.x;
    int tid = threadIdx.x;
    int b = r / TT, t = r % TT;
    const float* hrow = g_hdn + (size_t)r * DHALF;

    float p0 = 0.f, p1 = 0.f, p2 = 0.f;
    for (int j = tid; j < DHALF; j += 256) {
        float h = hrow[j];
        p0 = fmaf(h, rw2[j], p0);
        p1 = fmaf(h, rw2[DHALF + j], p1);
        p2 = fmaf(h, rw2[2 * DHALF + j], p2);
    }
    #pragma unroll
    for (int o = 16; o; o >>= 1) {
        p0 += __shfl_xor_sync(0xffffffffu, p0, o);
        p1 += __shfl_xor_sync(0xffffffffu, p1, o);
        p2 += __shfl_xor_sync(0xffffffffu, p2, o);
    }
    __shared__ float red0[8], red1[8], red2[8];
    __shared__ float lam[3];
    int lane = tid & 31, w = tid >> 5;
    if (lane == 0) { red0[w] = p0; red1[w] = p1; red2[w] = p2; }
    __syncthreads();
    if (tid == 0) {
        float l0 = rb2[0], l1 = rb2[1], l2v = rb2[2];
        #pragma unroll
        for (int ww = 0; ww < 8; ww++) { l0 += red0[ww]; l1 += red1[ww]; l2v += red2[ww]; }
        float mx = fmaxf(l0, fmaxf(l1, l2v));
        float e0 = expf(l0 - mx), e1 = expf(l1 - mx), e2 = expf(l2v - mx);
        float inv = 1.f / (e0 + e1 + e2);
        lam[0] = e0 * inv; lam[1] = e1 * inv; lam[2] = e2 * inv;
        lam_out[r * 3 + 0] = lam[0];
        lam_out[r * 3 + 1] = lam[1];
        lam_out[r * 3 + 2] = lam[2];
    }
    __syncthreads();
    float la = lam[0], lb = lam[1], lcc = lam[2];

    int c = t / LCH, p = t % LCH;
    float pb = __powf(0.9f, (float)(p + 1));
    const float* carr = g_carry + c * BD + b * DD;
    size_t ro = (size_t)r * DD;
    for (int j = tid; j < DD; j += 256) {
        float l2v = g_l2[ro + j] + pb * carr[j];
        float v = la * x[ro + j] + lb * l2v + lcc * l3mem[b * DD + j];
        __half hv = __float2half_rn(v);
        g_f16h[ro + j] = hv;
        g_f16l[ro + j] = __float2half_rn(v - __half2float(hv));
    }
}

// ================= launch =================
extern "C" void kernel_launch(void* const* d_in, const int* in_sizes, int n_in,
                              void* d_out, int out_size) {
    (void)in_sizes; (void)n_in; (void)out_size;
    const float* x    = (const float*)d_in[0];
    const float* l3m  = (const float*)d_in[1];
    const float* wq   = (const float*)d_in[2];
    const float* wk   = (const float*)d_in[3];
    const float* wv   = (const float*)d_in[4];
    const float* wo   = (const float*)d_in[5];
    const float* rw1  = (const float*)d_in[6];
    const float* rb1  = (const float*)d_in[7];
    const float* rw2  = (const float*)d_in[8];
    const float* rb2  = (const float*)d_in[9];

    float* out     = (float*)d_out;
    float* kh_out  = out + (size_t)RR * DD;
    float* vh_out  = kh_out + (size_t)RR * DD;
    float* lam_out = vh_out + (size_t)RR * DD;

    float* hdn_;
    cudaGetSymbolAddress((void**)&hdn_, g_hdn);

    __half *x16h,*x16l,*q16h,*q16l,*f16h,*f16l,*a16h,*a16l;
    __half *wq16,*wk16,*wv16,*wo16,*r116;
    cudaGetSymbolAddress((void**)&x16h, g_x16h); cudaGetSymbolAddress((void**)&x16l, g_x16l);
    cudaGetSymbolAddress((void**)&q16h, g_q16h); cudaGetSymbolAddress((void**)&q16l, g_q16l);
    cudaGetSymbolAddress((void**)&f16h, g_f16h); cudaGetSymbolAddress((void**)&f16l, g_f16l);
    cudaGetSymbolAddress((void**)&a16h, g_a16h); cudaGetSymbolAddress((void**)&a16l, g_a16l);
    cudaGetSymbolAddress((void**)&wq16, g_wq16); cudaGetSymbolAddress((void**)&wk16, g_wk16);
    cudaGetSymbolAddress((void**)&wv16, g_wv16); cudaGetSymbolAddress((void**)&wo16, g_wo16);
    cudaGetSymbolAddress((void**)&r116, g_r116);

    __nv_bfloat16 *qhi,*qlo,*khhi,*khlo,*vhhi,*vhlo;
    cudaGetSymbolAddress((void**)&qhi, g_qhi);   cudaGetSymbolAddress((void**)&qlo, g_qlo);
    cudaGetSymbolAddress((void**)&khhi, g_khhi); cudaGetSymbolAddress((void**)&khlo, g_khlo);
    cudaGetSymbolAddress((void**)&vhhi, g_vhhi); cudaGetSymbolAddress((void**)&vhlo, g_vhlo);

    cudaFuncSetAttribute(gemm_f16<0>, cudaFuncAttributeMaxDynamicSharedMemorySize, SMEM_GEMM);
    cudaFuncSetAttribute(gemm_f16<1>, cudaFuncAttributeMaxDynamicSharedMemorySize, SMEM_GEMM);
    cudaFuncSetAttribute(gemm_f16<2>, cudaFuncAttributeMaxDynamicSharedMemorySize, SMEM_GEMM);
    cudaFuncSetAttribute(gemm_kv_f16, cudaFuncAttributeMaxDynamicSharedMemorySize, SMEM_GEMM);
    cudaFuncSetAttribute(flash_attn,  cudaFuncAttributeMaxDynamicSharedMemorySize, SMEM_FLASH);

    const int NBIG = RR * DD / 4;
    const int NR1  = DHALF * DD / 4;

    // conversions: x -> fp16 split; weights -> fp16 hi only
    CvtArgs ca;
    ca.src[0] = (const float4*)x;   ca.h[0] = (__half2*)x16h; ca.l[0] = (__half2*)x16l; ca.n4[0] = NBIG;
    ca.src[1] = (const float4*)wq;  ca.h[1] = (__half2*)wq16; ca.l[1] = nullptr;        ca.n4[1] = NBIG;
    ca.src[2] = (const float4*)wk;  ca.h[2] = (__half2*)wk16; ca.l[2] = nullptr;        ca.n4[2] = NBIG;
    ca.src[3] = (const float4*)wv;  ca.h[3] = (__half2*)wv16; ca.l[3] = nullptr;        ca.n4[3] = NBIG;
    ca.src[4] = (const float4*)wo;  ca.h[4] = (__half2*)wo16; ca.l[4] = nullptr;        ca.n4[4] = NBIG;
    ca.src[5] = (const float4*)rw1; ca.h[5] = (__half2*)r116; ca.l[5] = nullptr;        ca.n4[5] = NR1;
    cvt_all<<<dim3(NBIG/256, 6), 256>>>(ca);

    ema_pass1<<<BB * NC * DD / 256, 256>>>(x);
    ema_pass2<<<BD / 256, 256>>>();

    // q = x @ wq^T (bf16 pair for flash + fp16 pair for hdn)
    gemm_f16<2><<<dim3(DD/128, RR/64), 128, SMEM_GEMM>>>(x16h, x16l, wq16, nullptr, qhi, qlo, DD, nullptr);
    // hdn = silu(q @ rw1^T + rb1)
    gemm_f16<1><<<dim3(DHALF/128, RR/64), 128, SMEM_GEMM>>>(q16h, q16l, r116, hdn_, nullptr, nullptr, DHALF, rb1);
    // router + fuse (emits fused fp16 pair)
    router_fuse<<<RR, 256>>>(x, l3m, rw2, rb2, lam_out);
    // K and V projections in one launch
    gemm_kv_f16<<<dim3(DD/128, RR/64, 2), 128, SMEM_GEMM>>>(f16h, f16l,
        kh_out, khhi, khlo, vh_out, vhhi, vhlo);
    // fused attention (bf16 3-product)
    flash_attn<<<dim3(BB*HH, TT/128), 256, SMEM_FLASH>>>(khhi, khlo, vhhi, vhlo);
    // out = attno @ wo^T
    gemm_f16<0><<<dim3(DD/128, RR/64), 128, SMEM_GEMM>>>(a16h, a16l, wo16, out, nullptr, nullptr, DD, nullptr);
}

// round 17
// speedup vs baseline: 1.7722x; 1.1841x over previous
#include <cuda_runtime.h>
#include <cuda_bf16.h>
#include <cuda_fp16.h>
#include <math.h>
#include <stdint.h>

// Problem constants
#define BB 2
#define TT 1024
#define DD 2048
#define HH 16
#define DHD 128
#define RR (BB*TT)       // 2048
#define DHALF (DD/2)     // 1024
#define LCH 128
#define NC (TT/LCH)
#define BD (BB*DD)

#define KDIM 2048
#define NCH2 (KDIM/128)                       // 16 chunks of 128 halves (256B rows)
#define STAGE_F16 49152                       // A 16K + B 32K
#define SMEM_GEMM (2*STAGE_F16 + 1024)        // ~97KB -> 2 CTAs/SM
#define SMEM_FLASH (65536 + 2*65536 + 1024)   // Q + 2 KV stages

// -------- fp32 scratch --------
__device__ float g_hdn[RR*DHALF];
__device__ float g_l2[RR*DD];
__device__ float g_fin[NC*BD];
__device__ float g_carry[NC*BD];

// -------- fp16 scratch (1-product GEMM path) --------
__device__ __half g_x16[RR*DD];
__device__ __half g_q16[RR*DD];
__device__ __half g_f16[RR*DD];
__device__ __half g_a16[RR*DD];
__device__ __half g_wq16[DD*DD], g_wk16[DD*DD], g_wv16[DD*DD], g_wo16[DD*DD];
__device__ __half g_r116[DHALF*DD];

// -------- bf16 hi/lo scratch (flash attention path) --------
__device__ __nv_bfloat16 g_qhi[RR*DD],  g_qlo[RR*DD];
__device__ __nv_bfloat16 g_khhi[RR*DD], g_khlo[RR*DD];   // [b,h,t,dh]
__device__ __nv_bfloat16 g_vhhi[RR*DD], g_vhlo[RR*DD];   // [b,h,t,dh]

// ================= PTX helpers =================
__device__ __forceinline__ uint32_t smem_u32(const void* p) {
    uint32_t a;
    asm("{ .reg .u64 t; cvta.to.shared.u64 t, %1; cvt.u32.u64 %0, t; }" : "=r"(a) : "l"(p));
    return a;
}
__device__ __forceinline__ void cpasync16(uint32_t s, const void* g) {
    asm volatile("cp.async.cg.shared.global [%0], [%1], 16;" :: "r"(s), "l"(g));
}
#define CP_COMMIT() asm volatile("cp.async.commit_group;" ::: "memory")
#define CP_WAIT(n)  asm volatile("cp.async.wait_group %0;" :: "n"(n) : "memory")

__device__ __forceinline__ void ldsm4(uint32_t* r, uint32_t addr) {
    asm volatile("ldmatrix.sync.aligned.m8n8.x4.shared.b16 {%0,%1,%2,%3}, [%4];"
        : "=r"(r[0]), "=r"(r[1]), "=r"(r[2]), "=r"(r[3]) : "r"(addr));
}
__device__ __forceinline__ void ldsm4t(uint32_t* r, uint32_t addr) {
    asm volatile("ldmatrix.sync.aligned.m8n8.x4.trans.shared.b16 {%0,%1,%2,%3}, [%4];"
        : "=r"(r[0]), "=r"(r[1]), "=r"(r[2]), "=r"(r[3]) : "r"(addr));
}
__device__ __forceinline__ void mma16816(float* c, const uint32_t* a, const uint32_t* b) {
    asm volatile(
        "mma.sync.aligned.m16n8k16.row.col.f32.bf16.bf16.f32 "
        "{%0,%1,%2,%3}, {%4,%5,%6,%7}, {%8,%9}, {%0,%1,%2,%3};"
        : "+f"(c[0]), "+f"(c[1]), "+f"(c[2]), "+f"(c[3])
        : "r"(a[0]), "r"(a[1]), "r"(a[2]), "r"(a[3]), "r"(b[0]), "r"(b[1]));
}
__device__ __forceinline__ void mma16816h(float* c, const uint32_t* a, const uint32_t* b) {
    asm volatile(
        "mma.sync.aligned.m16n8k16.row.col.f32.f16.f16.f32 "
        "{%0,%1,%2,%3}, {%4,%5,%6,%7}, {%8,%9}, {%0,%1,%2,%3};"
        : "+f"(c[0]), "+f"(c[1]), "+f"(c[2]), "+f"(c[3])
        : "r"(a[0]), "r"(a[1]), "r"(a[2]), "r"(a[3]), "r"(b[0]), "r"(b[1]));
}
__device__ __forceinline__ void pack_hilo(float x, float y, uint32_t& hi, uint32_t& lo) {
    __nv_bfloat16 hx = __float2bfloat16(x), hy = __float2bfloat16(y);
    __nv_bfloat16 lx = __float2bfloat16(x - __bfloat162float(hx));
    __nv_bfloat16 ly = __float2bfloat16(y - __bfloat162float(hy));
    __nv_bfloat162 hp(hx, hy), lp(lx, ly);
    hi = *(uint32_t*)&hp; lo = *(uint32_t*)&lp;
}
__device__ __forceinline__ uint32_t pack_f16(float x, float y) {
    __half2 hp(__float2half_rn(x), __float2half_rn(y));
    return *(uint32_t*)&hp;
}

// ============ conversion: all six tensors -> fp16 (round-to-nearest) =======
struct CvtArgs {
    const float4* src[6];
    __half2* h[6];
    int n4[6];
};
__global__ void cvt_all(CvtArgs a) {
    int t = blockIdx.y;
    int i = blockIdx.x * blockDim.x + threadIdx.x;
    if (i >= a.n4[t]) return;
    float4 v = a.src[t][i];
    a.h[t][2*i]   = __half2(__float2half_rn(v.x), __float2half_rn(v.y));
    a.h[t][2*i+1] = __half2(__float2half_rn(v.z), __float2half_rn(v.w));
}

// ================= fp16 1-product GEMM core ================================
// C = Ah * Bh^T.  64x128 CTA tile, 128 threads (2x2 warps of 32x64),
// BK=128 halves (256B rows), 2-stage cp.async pipeline, 2 CTAs/SM.
// Swizzle: unit j (16B) of row m at j ^ (m & 7)  (XOR on low 3 unit bits).
struct GemmF16 {
    uint32_t sb;
    int tid, wid, lane, wm, wn;
    int aRow0, aKh, bRow0, bKh;
    const char *gA0, *gB0;
    float acc[2][8][4];

    __device__ __forceinline__ void init(char* dsm, int m0, int n0,
        const __half* Ah, const __half* Bh) {
        tid = threadIdx.x; wid = tid >> 5; lane = tid & 31;
        wm = (wid & 1) * 32; wn = (wid >> 1) * 64;
        sb = (smem_u32(dsm) + 1023u) & ~1023u;
        gA0 = (const char*)(Ah + (size_t)m0 * KDIM);
        gB0 = (const char*)(Bh + (size_t)n0 * KDIM);
        #pragma unroll
        for (int i = 0; i < 2; i++)
            #pragma unroll
            for (int j = 0; j < 8; j++)
                #pragma unroll
                for (int r = 0; r < 4; r++) acc[i][j][r] = 0.f;
        aRow0 = wm + ((lane >> 3) & 1) * 8 + (lane & 7);
        aKh   = (lane >> 4) & 1;
        bRow0 = wn + ((lane >> 4) & 1) * 8 + (lane & 7);
        bKh   = (lane >> 3) & 1;
    }

    __device__ __forceinline__ void load_stage(int s, int c) {
        uint32_t base = sb + (uint32_t)s * STAGE_F16;
        const int kb = c * 256;   // byte offset in K (128 halves)
        #pragma unroll
        for (int it = 0; it < 8; it++) {
            int idx = tid + it * 128;                  // 0..1023 : A rows 0..63, j 0..15
            int m = idx >> 4, j = idx & 15;
            uint32_t off = (uint32_t)m * 256u + (uint32_t)((j ^ (m & 7)) << 4);
            size_t go = (size_t)m * (KDIM * 2) + kb + j * 16;
            cpasync16(base + off, gA0 + go);
        }
        #pragma unroll
        for (int it = 0; it < 16; it++) {
            int idx = tid + it * 128;                  // 0..2047 : B rows 0..127
            int m = idx >> 4, j = idx & 15;
            uint32_t off = (uint32_t)m * 256u + (uint32_t)((j ^ (m & 7)) << 4);
            size_t go = (size_t)m * (KDIM * 2) + kb + j * 16;
            cpasync16(base + 16384u + off, gB0 + go);
        }
        CP_COMMIT();
    }

    __device__ __forceinline__ void run() {
        load_stage(0, 0);
        load_stage(1, 1);
        #pragma unroll 1
        for (int c = 0; c < NCH2; c++) {
            if (c + 2 < NCH2) { CP_WAIT(1); } else { CP_WAIT(0); }
            __syncthreads();
            uint32_t base = sb + (uint32_t)(c & 1) * STAGE_F16;
            #pragma unroll
            for (int kk = 0; kk < 8; kk++) {
                uint32_t ah[2][4];
                #pragma unroll
                for (int mt = 0; mt < 2; mt++) {
                    int row = aRow0 + mt * 16;
                    int cc = (kk * 2 + aKh) ^ (row & 7);
                    uint32_t off = (uint32_t)row * 256u + (uint32_t)cc * 16u;
                    ldsm4(ah[mt], base + off);
                }
                #pragma unroll
                for (int g = 0; g < 4; g++) {
                    uint32_t bh[4];
                    int row = bRow0 + g * 16;
                    int cc = (kk * 2 + bKh) ^ (row & 7);
                    uint32_t off = (uint32_t)row * 256u + (uint32_t)cc * 16u;
                    ldsm4(bh, base + 16384u + off);
                    #pragma unroll
                    for (int i = 0; i < 2; i++)
                        #pragma unroll
                        for (int jj = 0; jj < 2; jj++)
                            mma16816h(acc[i][g * 2 + jj], ah[i], &bh[jj * 2]);
                }
            }
            __syncthreads();
            if (c + 2 < NCH2) load_stage(c & 1, c + 2);
        }
    }
};

// ================= fp16 GEMM kernels =======================================
// MODE 0: fp32 plain (out)   MODE 1: bias+silu fp32 (hdn)
// MODE 2: Q — bf16 hi/lo (flash) + fp16 (hdn input)
template<int MODE>
__global__ void __launch_bounds__(128, 2)
gemm_f16(const __half* __restrict__ Ah, const __half* __restrict__ Bh,
         float* __restrict__ C, __nv_bfloat16* __restrict__ Chi,
         __nv_bfloat16* __restrict__ Clo, int ldc, const float* __restrict__ bias) {
    extern __shared__ char dsm[];
    const int m0 = blockIdx.y * 64, n0 = blockIdx.x * 128;
    GemmF16 gc;
    gc.init(dsm, m0, n0, Ah, Bh);
    gc.run();

    #pragma unroll
    for (int i = 0; i < 2; i++) {
        #pragma unroll
        for (int j = 0; j < 8; j++) {
            #pragma unroll
            for (int rr = 0; rr < 2; rr++) {
                int row = m0 + gc.wm + i * 16 + (gc.lane >> 2) + rr * 8;
                int col = n0 + gc.wn + j * 8 + (gc.lane & 3) * 2;
                float v0 = gc.acc[i][j][rr * 2 + 0];
                float v1 = gc.acc[i][j][rr * 2 + 1];
                if (MODE == 0) {
                    *(float2*)(C + (size_t)row * ldc + col) = make_float2(v0, v1);
                } else if (MODE == 1) {
                    v0 += bias[col];     v1 += bias[col + 1];
                    v0 = v0 / (1.f + expf(-v0));
                    v1 = v1 / (1.f + expf(-v1));
                    *(float2*)(C + (size_t)row * ldc + col) = make_float2(v0, v1);
                } else {  // MODE 2 (Q)
                    size_t idx = (size_t)row * ldc + col;
                    uint32_t hp, lp; pack_hilo(v0, v1, hp, lp);
                    *(uint32_t*)(Chi + idx) = hp;
                    *(uint32_t*)(Clo + idx) = lp;
                    *(uint32_t*)(g_q16 + idx) = pack_f16(v0, v1);
                }
            }
        }
    }
}

// K and V projections merged into one launch (z selects pair).
__global__ void __launch_bounds__(128, 2)
gemm_kv_f16(const __half* __restrict__ Ah,
            float* __restrict__ Ck, __nv_bfloat16* __restrict__ Ckhi, __nv_bfloat16* __restrict__ Cklo,
            float* __restrict__ Cv, __nv_bfloat16* __restrict__ Cvhi, __nv_bfloat16* __restrict__ Cvlo) {
    extern __shared__ char dsm[];
    const int m0 = blockIdx.y * 64, n0 = blockIdx.x * 128;
    const int zz = blockIdx.z;
    const __half* Bh = zz ? g_wv16 : g_wk16;
    float* C            = zz ? Cv   : Ck;
    __nv_bfloat16* Chi  = zz ? Cvhi : Ckhi;
    __nv_bfloat16* Clo  = zz ? Cvlo : Cklo;

    GemmF16 gc;
    gc.init(dsm, m0, n0, Ah, Bh);
    gc.run();

    #pragma unroll
    for (int i = 0; i < 2; i++) {
        #pragma unroll
        for (int j = 0; j < 8; j++) {
            #pragma unroll
            for (int rr = 0; rr < 2; rr++) {
                int row = m0 + gc.wm + i * 16 + (gc.lane >> 2) + rr * 8;
                int col = n0 + gc.wn + j * 8 + (gc.lane & 3) * 2;
                float v0 = gc.acc[i][j][rr * 2 + 0];
                float v1 = gc.acc[i][j][rr * 2 + 1];
                int b = row >> 10, t = row & 1023;
                int h = col >> 7,  jj = col & 127;
                size_t idx = (((size_t)(b * HH + h)) * TT + t) * DHD + jj;
                *(float2*)(C + idx) = make_float2(v0, v1);
                uint32_t hp, lp; pack_hilo(v0, v1, hp, lp);
                *(uint32_t*)(Chi + idx) = hp;
                *(uint32_t*)(Clo + idx) = lp;
            }
        }
    }
}

// ================= flash attention (fused S, softmax, PV; bf16 3-product) ==
__global__ void __launch_bounds__(256, 1)
flash_attn(const __nv_bfloat16* __restrict__ khhi, const __nv_bfloat16* __restrict__ khlo,
           const __nv_bfloat16* __restrict__ vhhi, const __nv_bfloat16* __restrict__ vhlo) {
    extern __shared__ char dsm[];
    const int z  = blockIdx.x;
    const int qi = (int)gridDim.y - 1 - (int)blockIdx.y;
    const int b = z >> 4, h = z & 15;
    const int m0 = qi * 128;
    const int tid = threadIdx.x, wid = tid >> 5, lane = tid & 31;
    uint32_t sb = (smem_u32(dsm) + 1023u) & ~1023u;
    const uint32_t qs = sb;

    {
        const __nv_bfloat16* Qh = g_qhi + ((size_t)(b * TT) + m0) * DD + h * DHD;
        const __nv_bfloat16* Ql = g_qlo + ((size_t)(b * TT) + m0) * DD + h * DHD;
        #pragma unroll
        for (int it = 0; it < 8; it++) {
            int idx = tid + it * 256;
            int row = idx >> 4, u = idx & 15;
            uint32_t sa = qs + (uint32_t)row * 256u + (uint32_t)((u ^ (row & 7)) << 4);
            cpasync16(sa,           Qh + (size_t)row * DD + u * 8);
            cpasync16(sa + 32768u,  Ql + (size_t)row * DD + u * 8);
        }
    }
    const __nv_bfloat16* Kh = khhi + (size_t)z * TT * DHD;
    const __nv_bfloat16* Kl = khlo + (size_t)z * TT * DHD;
    const __nv_bfloat16* Vh = vhhi + (size_t)z * TT * DHD;
    const __nv_bfloat16* Vl = vhlo + (size_t)z * TT * DHD;

    auto load_kv = [&](int s, int ch) {
        uint32_t base = sb + 65536u + (uint32_t)s * 65536u;
        const __nv_bfloat16* srcs[4] = {
            Kh + (size_t)ch * 64 * DHD, Kl + (size_t)ch * 64 * DHD,
            Vh + (size_t)ch * 64 * DHD, Vl + (size_t)ch * 64 * DHD };
        #pragma unroll
        for (int tI = 0; tI < 4; tI++) {
            uint32_t tb = base + (uint32_t)tI * 16384u;
            const __nv_bfloat16* g = srcs[tI];
            #pragma unroll
            for (int it = 0; it < 4; it++) {
                int idx = tid + it * 256;
                int row = idx >> 4, u = idx & 15;
                cpasync16(tb + (uint32_t)row * 256u + (uint32_t)((u ^ (row & 7)) << 4),
                          g + (size_t)row * DHD + u * 8);
            }
        }
        CP_COMMIT();
    };

    const int nch = 2 * qi + 2;
    load_kv(0, 0);

    float m_[2] = {-1e30f, -1e30f}, l_[2] = {0.f, 0.f};
    float oacc[16][4];
    #pragma unroll
    for (int j = 0; j < 16; j++)
        #pragma unroll
        for (int r = 0; r < 4; r++) oacc[j][r] = 0.f;

    const int qrow_lo = wid * 16 + (lane >> 2);
    const float scale = 0.08838834764831845f;

    #pragma unroll 1
    for (int ch = 0; ch < nch; ch++) {
        if (ch + 1 < nch) {
            load_kv((ch + 1) & 1, ch + 1);
            CP_WAIT(1);
        } else {
            CP_WAIT(0);
        }
        __syncthreads();
        uint32_t kb = sb + 65536u + (uint32_t)(ch & 1) * 65536u;
        uint32_t vb = kb + 32768u;

        float sacc[8][4];
        #pragma unroll
        for (int j = 0; j < 8; j++)
            #pragma unroll
            for (int r = 0; r < 4; r++) sacc[j][r] = 0.f;

        #pragma unroll
        for (int kk = 0; kk < 8; kk++) {
            uint32_t ah[4], al[4];
            int arow = wid * 16 + ((lane >> 3) & 1) * 8 + (lane & 7);
            int au = (kk * 2 + ((lane >> 4) & 1)) ^ (arow & 7);
            uint32_t aoff = (uint32_t)arow * 256u + (uint32_t)au * 16u;
            ldsm4(ah, qs + aoff);
            ldsm4(al, qs + 32768u + aoff);
            #pragma unroll
            for (int g = 0; g < 4; g++) {
                uint32_t bh_[4], bl_[4];
                int brow = g * 16 + ((lane >> 4) & 1) * 8 + (lane & 7);
                int bu = (kk * 2 + ((lane >> 3) & 1)) ^ (brow & 7);
                uint32_t boff = (uint32_t)brow * 256u + (uint32_t)bu * 16u;
                ldsm4(bh_, kb + boff);
                ldsm4(bl_, kb + 16384u + boff);
                #pragma unroll
                for (int jj = 0; jj < 2; jj++) {
                    int j = g * 2 + jj;
                    mma16816(sacc[j], ah, &bh_[jj * 2]);
                    mma16816(sacc[j], ah, &bl_[jj * 2]);
                    mma16816(sacc[j], al, &bh_[jj * 2]);
                }
            }
        }

        const int kvbase = ch * 64;
        const bool maskp = (kvbase + 63 > m0);
        float mx[2] = {-1e30f, -1e30f};
        #pragma unroll
        for (int j = 0; j < 8; j++)
            #pragma unroll
            for (int r = 0; r < 4; r++) {
                float v = sacc[j][r] * scale;
                if (maskp) {
                    int col_g = kvbase + 8 * j + 2 * (lane & 3) + (r & 1);
                    int row_g = m0 + qrow_lo + (r >> 1) * 8;
                    if (col_g > row_g) v = -1e30f;
                }
                sacc[j][r] = v;
                mx[r >> 1] = fmaxf(mx[r >> 1], v);
            }
        #pragma unroll
        for (int rr = 0; rr < 2; rr++) {
            mx[rr] = fmaxf(mx[rr], __shfl_xor_sync(0xffffffffu, mx[rr], 1));
            mx[rr] = fmaxf(mx[rr], __shfl_xor_sync(0xffffffffu, mx[rr], 2));
        }
        float mn0 = fmaxf(m_[0], mx[0]), mn1 = fmaxf(m_[1], mx[1]);
        float al0 = __expf(m_[0] - mn0), al1 = __expf(m_[1] - mn1);
        float rs[2] = {0.f, 0.f};
        #pragma unroll
        for (int j = 0; j < 8; j++)
            #pragma unroll
            for (int r = 0; r < 4; r++) {
                float p = __expf(sacc[j][r] - ((r >> 1) ? mn1 : mn0));
                sacc[j][r] = p;
                rs[r >> 1] += p;
            }
        #pragma unroll
        for (int rr = 0; rr < 2; rr++) {
            rs[rr] += __shfl_xor_sync(0xffffffffu, rs[rr], 1);
            rs[rr] += __shfl_xor_sync(0xffffffffu, rs[rr], 2);
        }
        l_[0] = l_[0] * al0 + rs[0];
        l_[1] = l_[1] * al1 + rs[1];
        m_[0] = mn0; m_[1] = mn1;
        #pragma unroll
        for (int j = 0; j < 16; j++) {
            oacc[j][0] *= al0; oacc[j][1] *= al0;
            oacc[j][2] *= al1; oacc[j][3] *= al1;
        }

        #pragma unroll
        for (int kk = 0; kk < 4; kk++) {
            uint32_t aph[4], apl[4];
            pack_hilo(sacc[2*kk][0],   sacc[2*kk][1],   aph[0], apl[0]);
            pack_hilo(sacc[2*kk][2],   sacc[2*kk][3],   aph[1], apl[1]);
            pack_hilo(sacc[2*kk+1][0], sacc[2*kk+1][1], aph[2], apl[2]);
            pack_hilo(sacc[2*kk+1][2], sacc[2*kk+1][3], aph[3], apl[3]);
            int krow = kk * 16 + ((lane >> 3) & 1) * 8 + (lane & 7);
            #pragma unroll
            for (int ng = 0; ng < 8; ng++) {
                int nchk = ng * 2 + (lane >> 4);
                uint32_t addr = vb + (uint32_t)krow * 256u
                              + (uint32_t)((nchk ^ (krow & 7)) << 4);
                uint32_t bvh[4], bvl[4];
                ldsm4t(bvh, addr);
                ldsm4t(bvl, addr + 16384u);
                #pragma unroll
                for (int jj = 0; jj < 2; jj++) {
                    int j = ng * 2 + jj;
                    mma16816(oacc[j], aph, &bvh[jj * 2]);
                    mma16816(oacc[j], aph, &bvl[jj * 2]);
                    mma16816(oacc[j], apl, &bvh[jj * 2]);
                }
            }
        }
        __syncthreads();
    }

    // epilogue: attno as fp16 for the out-projection
    float inv0 = 1.f / l_[0], inv1 = 1.f / l_[1];
    #pragma unroll
    for (int j = 0; j < 16; j++)
        #pragma unroll
        for (int rr = 0; rr < 2; rr++) {
            int t = m0 + qrow_lo + rr * 8;
            int col = 8 * j + 2 * (lane & 3);
            float inv = rr ? inv1 : inv0;
            float v0 = oacc[j][rr * 2 + 0] * inv;
            float v1 = oacc[j][rr * 2 + 1] * inv;
            size_t idx = ((size_t)(b * TT) + t) * DD + h * DHD + col;
            *(uint32_t*)(g_a16 + idx) = pack_f16(v0, v1);
        }
}

// ================= EMA (chunked parallel scan) =================
__global__ void ema_pass1(const float* __restrict__ x) {
    int idx = blockIdx.x * blockDim.x + threadIdx.x;
    int d = idx % DD;
    int c = (idx / DD) % NC;
    int b = idx / (DD * NC);
    const float beta = 0.9f, om = 1.0f - 0.9f;
    size_t base = ((size_t)b * TT + (size_t)c * LCH) * DD + d;
    float s = 0.f;
    #pragma unroll 4
    for (int p = 0; p < LCH; p++) {
        s = beta * s + om * x[base + (size_t)p * DD];
        g_l2[base + (size_t)p * DD] = s;
    }
    g_fin[c * BD + b * DD + d] = s;
}
__global__ void ema_pass2() {
    int idx = blockIdx.x * blockDim.x + threadIdx.x;
    const float bl = __powf(0.9f, (float)LCH);
    float P = 0.f;
    g_carry[idx] = 0.f;
    for (int c = 1; c < NC; c++) {
        P = g_fin[(c - 1) * BD + idx] + bl * P;
        g_carry[c * BD + idx] = P;
    }
}

// ================= router + level fusion (emit fp16) =======================
__global__ void router_fuse(const float* __restrict__ x,
                            const float* __restrict__ l3mem,
                            const float* __restrict__ rw2,
                            const float* __restrict__ rb2,
                            float* __restrict__ lam_out) {
    int r = blockIdx.x;
    int tid = threadIdx.x;
    int b = r / TT, t = r % TT;
    const float* hrow = g_hdn + (size_t)r * DHALF;

    float p0 = 0.f, p1 = 0.f, p2 = 0.f;
    for (int j = tid; j < DHALF; j += 256) {
        float h = hrow[j];
        p0 = fmaf(h, rw2[j], p0);
        p1 = fmaf(h, rw2[DHALF + j], p1);
        p2 = fmaf(h, rw2[2 * DHALF + j], p2);
    }
    #pragma unroll
    for (int o = 16; o; o >>= 1) {
        p0 += __shfl_xor_sync(0xffffffffu, p0, o);
        p1 += __shfl_xor_sync(0xffffffffu, p1, o);
        p2 += __shfl_xor_sync(0xffffffffu, p2, o);
    }
    __shared__ float red0[8], red1[8], red2[8];
    __shared__ float lam[3];
    int lane = tid & 31, w = tid >> 5;
    if (lane == 0) { red0[w] = p0; red1[w] = p1; red2[w] = p2; }
    __syncthreads();
    if (tid == 0) {
        float l0 = rb2[0], l1 = rb2[1], l2v = rb2[2];
        #pragma unroll
        for (int ww = 0; ww < 8; ww++) { l0 += red0[ww]; l1 += red1[ww]; l2v += red2[ww]; }
        float mx = fmaxf(l0, fmaxf(l1, l2v));
        float e0 = expf(l0 - mx), e1 = expf(l1 - mx), e2 = expf(l2v - mx);
        float inv = 1.f / (e0 + e1 + e2);
        lam[0] = e0 * inv; lam[1] = e1 * inv; lam[2] = e2 * inv;
        lam_out[r * 3 + 0] = lam[0];
        lam_out[r * 3 + 1] = lam[1];
        lam_out[r * 3 + 2] = lam[2];
    }
    __syncthreads();
    float la = lam[0], lb = lam[1], lcc = lam[2];

    int c = t / LCH, p = t % LCH;
    float pb = __powf(0.9f, (float)(p + 1));
    const float* carr = g_carry + c * BD + b * DD;
    size_t ro = (size_t)r * DD;
    for (int j = tid; j < DD; j += 256) {
        float l2v = g_l2[ro + j] + pb * carr[j];
        float v = la * x[ro + j] + lb * l2v + lcc * l3mem[b * DD + j];
        g_f16[ro + j] = __float2half_rn(v);
    }
}

// ================= launch =================
extern "C" void kernel_launch(void* const* d_in, const int* in_sizes, int n_in,
                              void* d_out, int out_size) {
    (void)in_sizes; (void)n_in; (void)out_size;
    const float* x    = (const float*)d_in[0];
    const float* l3m  = (const float*)d_in[1];
    const float* wq   = (const float*)d_in[2];
    const float* wk   = (const float*)d_in[3];
    const float* wv   = (const float*)d_in[4];
    const float* wo   = (const float*)d_in[5];
    const float* rw1  = (const float*)d_in[6];
    const float* rb1  = (const float*)d_in[7];
    const float* rw2  = (const float*)d_in[8];
    const float* rb2  = (const float*)d_in[9];

    float* out     = (float*)d_out;
    float* kh_out  = out + (size_t)RR * DD;
    float* vh_out  = kh_out + (size_t)RR * DD;
    float* lam_out = vh_out + (size_t)RR * DD;

    float* hdn_;
    cudaGetSymbolAddress((void**)&hdn_, g_hdn);

    __half *x16,*q16,*f16,*a16,*wq16,*wk16,*wv16,*wo16,*r116;
    cudaGetSymbolAddress((void**)&x16, g_x16);   cudaGetSymbolAddress((void**)&q16, g_q16);
    cudaGetSymbolAddress((void**)&f16, g_f16);   cudaGetSymbolAddress((void**)&a16, g_a16);
    cudaGetSymbolAddress((void**)&wq16, g_wq16); cudaGetSymbolAddress((void**)&wk16, g_wk16);
    cudaGetSymbolAddress((void**)&wv16, g_wv16); cudaGetSymbolAddress((void**)&wo16, g_wo16);
    cudaGetSymbolAddress((void**)&r116, g_r116);

    __nv_bfloat16 *qhi,*qlo,*khhi,*khlo,*vhhi,*vhlo;
    cudaGetSymbolAddress((void**)&qhi, g_qhi);   cudaGetSymbolAddress((void**)&qlo, g_qlo);
    cudaGetSymbolAddress((void**)&khhi, g_khhi); cudaGetSymbolAddress((void**)&khlo, g_khlo);
    cudaGetSymbolAddress((void**)&vhhi, g_vhhi); cudaGetSymbolAddress((void**)&vhlo, g_vhlo);

    cudaFuncSetAttribute(gemm_f16<0>, cudaFuncAttributeMaxDynamicSharedMemorySize, SMEM_GEMM);
    cudaFuncSetAttribute(gemm_f16<1>, cudaFuncAttributeMaxDynamicSharedMemorySize, SMEM_GEMM);
    cudaFuncSetAttribute(gemm_f16<2>, cudaFuncAttributeMaxDynamicSharedMemorySize, SMEM_GEMM);
    cudaFuncSetAttribute(gemm_kv_f16, cudaFuncAttributeMaxDynamicSharedMemorySize, SMEM_GEMM);
    cudaFuncSetAttribute(flash_attn,  cudaFuncAttributeMaxDynamicSharedMemorySize, SMEM_FLASH);

    const int NBIG = RR * DD / 4;
    const int NR1  = DHALF * DD / 4;

    // conversions: everything -> single fp16
    CvtArgs ca;
    ca.src[0] = (const float4*)x;   ca.h[0] = (__half2*)x16;  ca.n4[0] = NBIG;
    ca.src[1] = (const float4*)wq;  ca.h[1] = (__half2*)wq16; ca.n4[1] = NBIG;
    ca.src[2] = (const float4*)wk;  ca.h[2] = (__half2*)wk16; ca.n4[2] = NBIG;
    ca.src[3] = (const float4*)wv;  ca.h[3] = (__half2*)wv16; ca.n4[3] = NBIG;
    ca.src[4] = (const float4*)wo;  ca.h[4] = (__half2*)wo16; ca.n4[4] = NBIG;
    ca.src[5] = (const float4*)rw1; ca.h[5] = (__half2*)r116; ca.n4[5] = NR1;
    cvt_all<<<dim3(NBIG/256, 6), 256>>>(ca);

    ema_pass1<<<BB * NC * DD / 256, 256>>>(x);
    ema_pass2<<<BD / 256, 256>>>();

    // q = x @ wq^T (bf16 pair for flash + fp16 for hdn)
    gemm_f16<2><<<dim3(DD/128, RR/64), 128, SMEM_GEMM>>>(x16, wq16, nullptr, qhi, qlo, DD, nullptr);
    // hdn = silu(q @ rw1^T + rb1)
    gemm_f16<1><<<dim3(DHALF/128, RR/64), 128, SMEM_GEMM>>>(q16, r116, hdn_, nullptr, nullptr, DHALF, rb1);
    // router + fuse (emits fused fp16)
    router_fuse<<<RR, 256>>>(x, l3m, rw2, rb2, lam_out);
    // K and V projections in one launch
    gemm_kv_f16<<<dim3(DD/128, RR/64, 2), 128, SMEM_GEMM>>>(f16,
        kh_out, khhi, khlo, vh_out, vhhi, vhlo);
    // fused attention (bf16 3-product)
    flash_attn<<<dim3(BB*HH, TT/128), 256, SMEM_FLASH>>>(khhi, khlo, vhhi, vhlo);
    // out = attno @ wo^T
    gemm_f16<0><<<dim3(DD/128, RR/64), 128, SMEM_GEMM>>>(a16, wo16, out, nullptr, nullptr, DD, nullptr);
}